// round 1
// baseline (speedup 1.0000x reference)
#include <cuda_runtime.h>
#include <math.h>

#define B_SZ   4096
#define H_SZ   256
#define K_SZ   16
#define D_SZ   512
#define IN_DIM 8
#define XP_DIM 64
#define LN_EPS 1e-5f

#define MT 64   // batch rows per GEMM block
#define NT 64   // n (output) chunk
#define KT 64   // d (reduction) chunk

// Scratch: raw post-tanh h2 [B][K][D] (128 MiB), per-(b,k) LN stats, gates.
__device__ float g_raw[(size_t)B_SZ * K_SZ * D_SZ];
__device__ float g_mean[B_SZ * K_SZ];
__device__ float g_rstd[B_SZ * K_SZ];
__device__ float g_gates[B_SZ * K_SZ];

// ---------------------------------------------------------------------------
// Kernel A: gating network. One block per batch row, 256 threads.
// logits = tanh(h_prev @ gw1 + gb1) @ gw2 + gb2 ; gates = softmax(logits)
// ---------------------------------------------------------------------------
__global__ void gating_kernel(const float* __restrict__ h_prev,
                              const float* __restrict__ gw1,
                              const float* __restrict__ gb1,
                              const float* __restrict__ gw2,
                              const float* __restrict__ gb2) {
    __shared__ float hs[H_SZ];
    __shared__ float ts[H_SZ];
    const int b   = blockIdx.x;
    const int tid = threadIdx.x;

    hs[tid] = h_prev[b * H_SZ + tid];
    __syncthreads();

    float acc = gb1[tid];
#pragma unroll 8
    for (int i = 0; i < H_SZ; i++)
        acc = fmaf(hs[i], gw1[i * H_SZ + tid], acc);
    ts[tid] = tanhf(acc);
    __syncthreads();

    if (tid < 32) {
        float lg = -1e30f;
        if (tid < K_SZ) {
            float l = gb2[tid];
#pragma unroll 8
            for (int i = 0; i < H_SZ; i++)
                l = fmaf(ts[i], gw2[i * K_SZ + tid], l);
            lg = l;
        }
        // softmax over 16 active lanes (lanes >=16 contribute 0)
        float m = lg;
#pragma unroll
        for (int o = 16; o > 0; o >>= 1)
            m = fmaxf(m, __shfl_xor_sync(0xffffffffu, m, o));
        float e = (tid < K_SZ) ? expf(lg - m) : 0.0f;
        float s = e;
#pragma unroll
        for (int o = 16; o > 0; o >>= 1)
            s += __shfl_xor_sync(0xffffffffu, s, o);
        if (tid < K_SZ)
            g_gates[b * K_SZ + tid] = e / s;
    }
}

// ---------------------------------------------------------------------------
// Kernel B: per-expert fused GEMM.
// Block (bx, k): rows b0..b0+63, one expert.
//   A[m][d]  = tanh(x_ext[b0+m,k] * w1[k,d] + b1[k,d])   (generated in smem)
//   h2[m][e] = tanh(sum_d A[m][d]*w2[k,d,e] + b2[k,e])
// Writes raw tanh values to g_raw, accumulates row sum/sumsq for LayerNorm.
// ---------------------------------------------------------------------------
__global__ void __launch_bounds__(256, 1)
expert_gemm_kernel(const float* __restrict__ x_ext,
                   const float* __restrict__ w1,
                   const float* __restrict__ b1,
                   const float* __restrict__ w2,
                   const float* __restrict__ b2) {
    extern __shared__ float sm[];
    float* As    = sm;                    // [D_SZ][MT]  (d-major, m contiguous)
    float* Ws    = sm + D_SZ * MT;        // [KT][NT]
    float* s_sum = Ws + KT * NT;          // [MT]
    float* s_sq  = s_sum + MT;            // [MT]
    __shared__ float s_x[MT];

    const int b0  = blockIdx.x * MT;
    const int k   = blockIdx.y;
    const int tid = threadIdx.x;

    if (tid < MT) {
        s_x[tid]   = x_ext[(b0 + tid) * K_SZ + k];
        s_sum[tid] = 0.0f;
        s_sq[tid]  = 0.0f;
    }
    __syncthreads();

    // Generate A in smem: As[d*MT + m]
    const float* w1k = w1 + k * D_SZ;
    const float* b1k = b1 + k * D_SZ;
    for (int idx = tid; idx < D_SZ * MT; idx += 256) {
        int m = idx & (MT - 1);
        int d = idx >> 6;                 // MT == 64
        As[idx] = tanhf(fmaf(s_x[m], w1k[d], b1k[d]));
    }
    __syncthreads();

    const int tm = tid >> 4;              // 0..15  -> 4 m rows each
    const int tn = tid & 15;              // 0..15  -> 4 n cols each
    const float* w2k = w2 + (size_t)k * D_SZ * D_SZ;
    const float* b2k = b2 + k * D_SZ;

    for (int nc = 0; nc < D_SZ; nc += NT) {
        float acc[4][4];
#pragma unroll
        for (int mi = 0; mi < 4; mi++)
#pragma unroll
            for (int ni = 0; ni < 4; ni++) acc[mi][ni] = 0.0f;

        for (int dt = 0; dt < D_SZ; dt += KT) {
            // Stage Ws[dd][n] = w2[k][dt+dd][nc+n]  (4096 floats, 4 float4/thread)
#pragma unroll
            for (int it = 0; it < (KT * NT / 4) / 256; it++) {
                int i   = tid + it * 256;
                int row = i >> 4;         // NT/4 == 16
                int c4  = i & 15;
                ((float4*)Ws)[i] =
                    *(const float4*)&w2k[(size_t)(dt + row) * D_SZ + nc + c4 * 4];
            }
            __syncthreads();

#pragma unroll 16
            for (int dd = 0; dd < KT; dd++) {
                float4 a  = *(float4*)&As[(dt + dd) * MT + tm * 4];
                float4 bb = *(float4*)&Ws[dd * NT + tn * 4];
                acc[0][0] = fmaf(a.x, bb.x, acc[0][0]);
                acc[0][1] = fmaf(a.x, bb.y, acc[0][1]);
                acc[0][2] = fmaf(a.x, bb.z, acc[0][2]);
                acc[0][3] = fmaf(a.x, bb.w, acc[0][3]);
                acc[1][0] = fmaf(a.y, bb.x, acc[1][0]);
                acc[1][1] = fmaf(a.y, bb.y, acc[1][1]);
                acc[1][2] = fmaf(a.y, bb.z, acc[1][2]);
                acc[1][3] = fmaf(a.y, bb.w, acc[1][3]);
                acc[2][0] = fmaf(a.z, bb.x, acc[2][0]);
                acc[2][1] = fmaf(a.z, bb.y, acc[2][1]);
                acc[2][2] = fmaf(a.z, bb.z, acc[2][2]);
                acc[2][3] = fmaf(a.z, bb.w, acc[2][3]);
                acc[3][0] = fmaf(a.w, bb.x, acc[3][0]);
                acc[3][1] = fmaf(a.w, bb.y, acc[3][1]);
                acc[3][2] = fmaf(a.w, bb.z, acc[3][2]);
                acc[3][3] = fmaf(a.w, bb.w, acc[3][3]);
            }
            __syncthreads();
        }

        // Epilogue for this n-chunk: +b2, tanh, stats, store raw
        const int e0 = nc + tn * 4;
        float bx = b2k[e0 + 0], by = b2k[e0 + 1], bz = b2k[e0 + 2], bw = b2k[e0 + 3];
#pragma unroll
        for (int mi = 0; mi < 4; mi++) {
            int m  = tm * 4 + mi;
            int gb = b0 + m;
            float4 v;
            v.x = tanhf(acc[mi][0] + bx);
            v.y = tanhf(acc[mi][1] + by);
            v.z = tanhf(acc[mi][2] + bz);
            v.w = tanhf(acc[mi][3] + bw);
            float ps  = v.x + v.y + v.z + v.w;
            float pss = v.x * v.x + v.y * v.y + v.z * v.z + v.w * v.w;
            atomicAdd(&s_sum[m], ps);
            atomicAdd(&s_sq[m], pss);
            *(float4*)&g_raw[((size_t)gb * K_SZ + k) * D_SZ + e0] = v;
        }
    }

    __syncthreads();
    if (tid < MT) {
        float mu  = s_sum[tid] * (1.0f / (float)D_SZ);
        float var = s_sq[tid] * (1.0f / (float)D_SZ) - mu * mu;
        g_mean[(b0 + tid) * K_SZ + k] = mu;
        g_rstd[(b0 + tid) * K_SZ + k] = rsqrtf(var + LN_EPS);
    }
}

// ---------------------------------------------------------------------------
// Kernel C: apply LN affine, gate-weighted expert sum -> theta, then x_prime.
// One block per batch row, 256 threads.
// Output layout: [x_prime (B*64) | theta (B*512)]
// ---------------------------------------------------------------------------
__global__ void combine_kernel(const float* __restrict__ x_l,
                               const float* __restrict__ ln_g,
                               const float* __restrict__ ln_b,
                               const float* __restrict__ theta0,
                               float* __restrict__ out) {
    __shared__ float sg[K_SZ], smu[K_SZ], srs[K_SZ];
    __shared__ float th[D_SZ];
    const int b   = blockIdx.x;
    const int tid = threadIdx.x;

    if (tid < K_SZ) {
        sg[tid]  = g_gates[b * K_SZ + tid];
        smu[tid] = g_mean[b * K_SZ + tid];
        srs[tid] = g_rstd[b * K_SZ + tid];
    }
    __syncthreads();

    const float* rawb = &g_raw[(size_t)b * K_SZ * D_SZ];
#pragma unroll
    for (int e = tid; e < D_SZ; e += 256) {
        float lg = ln_g[e], lb = ln_b[e];
        float acc = 0.0f;
#pragma unroll
        for (int kk = 0; kk < K_SZ; kk++) {
            float v  = rawb[kk * D_SZ + e];
            float nv = (v - smu[kk]) * srs[kk];
            acc = fmaf(sg[kk], fmaf(nv, lg, lb), acc);
        }
        float t = acc + theta0[e];
        th[e] = t;
        out[(size_t)B_SZ * XP_DIM + (size_t)b * D_SZ + e] = t;
    }
    __syncthreads();

    if (tid < XP_DIM) {
        float xp = 0.0f;
#pragma unroll
        for (int i = 0; i < IN_DIM; i++)
            xp = fmaf(x_l[b * IN_DIM + i], th[i * XP_DIM + tid], xp);
        out[b * XP_DIM + tid] = xp;
    }
}

// ---------------------------------------------------------------------------
extern "C" void kernel_launch(void* const* d_in, const int* in_sizes, int n_in,
                              void* d_out, int out_size) {
    const float* h_prev = (const float*)d_in[0];
    const float* x_l    = (const float*)d_in[1];
    const float* x_ext  = (const float*)d_in[2];
    const float* w1     = (const float*)d_in[3];
    const float* b1     = (const float*)d_in[4];
    const float* w2     = (const float*)d_in[5];
    const float* b2     = (const float*)d_in[6];
    const float* gw1    = (const float*)d_in[7];
    const float* gb1    = (const float*)d_in[8];
    const float* gw2    = (const float*)d_in[9];
    const float* gb2    = (const float*)d_in[10];
    const float* ln_g   = (const float*)d_in[11];
    const float* ln_b   = (const float*)d_in[12];
    const float* th0    = (const float*)d_in[13];
    float* out = (float*)d_out;

    size_t smem = (size_t)(D_SZ * MT + KT * NT + 2 * MT) * sizeof(float);
    cudaFuncSetAttribute(expert_gemm_kernel,
                         cudaFuncAttributeMaxDynamicSharedMemorySize, (int)smem);

    gating_kernel<<<B_SZ, 256>>>(h_prev, gw1, gb1, gw2, gb2);

    dim3 gridB(B_SZ / MT, K_SZ);
    expert_gemm_kernel<<<gridB, 256, smem>>>(x_ext, w1, b1, w2, b2);

    combine_kernel<<<B_SZ, 256>>>(x_l, ln_g, ln_b, th0, out);
}

// round 3
// speedup vs baseline: 3.5158x; 3.5158x over previous
#include <cuda_runtime.h>
#include <cuda_bf16.h>
#include <math.h>
#include <stdint.h>

#define B_SZ   4096
#define H_SZ   256
#define K_SZ   16
#define D_SZ   512
#define IN_DIM 8
#define XP_DIM 64
#define LN_EPS 1e-5f

// GEMM tiling
#define BM 64
#define BK 32
#define SA 40    // A smem row stride in bf16 (pad 8)
#define SB 520   // B smem row stride in bf16 (pad 8)
#define A_MAT_BYTES (BM * SA * 2)        // 5120
#define B_MAT_BYTES (BK * SB * 2)        // 33280
#define STAGE_BYTES (2 * A_MAT_BYTES + 2 * B_MAT_BYTES)  // 76800
#define GEMM_SMEM (2 * STAGE_BYTES)      // 153600

// ---------------- scratch -----------------------------------------------
__device__ float g_raw[(size_t)B_SZ * K_SZ * D_SZ];   // post-tanh h2
__device__ float g_mean[B_SZ * K_SZ];
__device__ float g_rstd[B_SZ * K_SZ];
__device__ float g_gates[B_SZ * K_SZ];
__device__ __nv_bfloat16 g_Bhi[(size_t)K_SZ * D_SZ * D_SZ]; // w2 hi, [k][d][e]
__device__ __nv_bfloat16 g_Blo[(size_t)K_SZ * D_SZ * D_SZ]; // w2 lo

// ---------------- helpers ------------------------------------------------
__device__ __forceinline__ float fast_tanh(float x) {
    float e = __expf(2.0f * x);
    return 1.0f - __fdividef(2.0f, e + 1.0f);
}

__device__ __forceinline__ uint32_t smem_u32(const void* p) {
    uint32_t a;
    asm("{ .reg .u64 t; cvta.to.shared.u64 t, %1; cvt.u32.u64 %0, t; }"
        : "=r"(a) : "l"(p));
    return a;
}

__device__ __forceinline__ void cp16(uint32_t dst, const void* src) {
    asm volatile("cp.async.cg.shared.global [%0], [%1], 16;" :: "r"(dst), "l"(src));
}

__device__ __forceinline__ void ldsm4(uint32_t* r, uint32_t a) {
    asm volatile("ldmatrix.sync.aligned.m8n8.x4.shared.b16 {%0,%1,%2,%3}, [%4];"
                 : "=r"(r[0]), "=r"(r[1]), "=r"(r[2]), "=r"(r[3]) : "r"(a));
}

__device__ __forceinline__ void ldsm4t(uint32_t* r, uint32_t a) {
    asm volatile("ldmatrix.sync.aligned.m8n8.x4.trans.shared.b16 {%0,%1,%2,%3}, [%4];"
                 : "=r"(r[0]), "=r"(r[1]), "=r"(r[2]), "=r"(r[3]) : "r"(a));
}

__device__ __forceinline__ void mma16816(float* c, const uint32_t* a,
                                         uint32_t b0, uint32_t b1) {
    asm volatile(
        "mma.sync.aligned.m16n8k16.row.col.f32.bf16.bf16.f32 "
        "{%0,%1,%2,%3}, {%4,%5,%6,%7}, {%8,%9}, {%0,%1,%2,%3};"
        : "+f"(c[0]), "+f"(c[1]), "+f"(c[2]), "+f"(c[3])
        : "r"(a[0]), "r"(a[1]), "r"(a[2]), "r"(a[3]), "r"(b0), "r"(b1));
}

// ---------------------------------------------------------------------------
// Prep: w2 fp32 -> hi/lo bf16 (same [k][d][e] layout). 2048 blocks x 256 thr.
// ---------------------------------------------------------------------------
__global__ void __launch_bounds__(256) prep_kernel(const float* __restrict__ w2) {
    size_t idx = ((size_t)blockIdx.x * 256 + threadIdx.x) * 8;
    float4 v0 = *(const float4*)(w2 + idx);
    float4 v1 = *(const float4*)(w2 + idx + 4);
    float v[8] = {v0.x, v0.y, v0.z, v0.w, v1.x, v1.y, v1.z, v1.w};
    union { __nv_bfloat16 h[8]; uint4 u; } H, L;
#pragma unroll
    for (int j = 0; j < 8; j++) {
        __nv_bfloat16 hi = __float2bfloat16(v[j]);
        H.h[j] = hi;
        L.h[j] = __float2bfloat16(v[j] - __bfloat162float(hi));
    }
    *(uint4*)(g_Bhi + idx) = H.u;
    *(uint4*)(g_Blo + idx) = L.u;
}

// ---------------------------------------------------------------------------
// Gating: 8 batch rows per block.
// ---------------------------------------------------------------------------
__global__ void __launch_bounds__(256) gating_kernel(
    const float* __restrict__ h_prev, const float* __restrict__ gw1,
    const float* __restrict__ gb1, const float* __restrict__ gw2,
    const float* __restrict__ gb2) {
    __shared__ float hsT[H_SZ * 8];
    __shared__ float ts[8 * H_SZ];
    const int b0 = blockIdx.x * 8;
    const int tid = threadIdx.x;

    for (int idx = tid; idx < 8 * H_SZ; idx += 256) {
        int r = idx >> 8, i = idx & 255;
        hsT[i * 8 + r] = h_prev[(b0 + r) * H_SZ + i];
    }
    __syncthreads();

    float acc[8];
    {
        float bb = gb1[tid];
#pragma unroll
        for (int r = 0; r < 8; r++) acc[r] = bb;
    }
#pragma unroll 4
    for (int i = 0; i < H_SZ; i++) {
        float w = gw1[i * H_SZ + tid];
        float4 a0 = *(const float4*)&hsT[i * 8];
        float4 a1 = *(const float4*)&hsT[i * 8 + 4];
        acc[0] = fmaf(a0.x, w, acc[0]);
        acc[1] = fmaf(a0.y, w, acc[1]);
        acc[2] = fmaf(a0.z, w, acc[2]);
        acc[3] = fmaf(a0.w, w, acc[3]);
        acc[4] = fmaf(a1.x, w, acc[4]);
        acc[5] = fmaf(a1.y, w, acc[5]);
        acc[6] = fmaf(a1.z, w, acc[6]);
        acc[7] = fmaf(a1.w, w, acc[7]);
    }
#pragma unroll
    for (int r = 0; r < 8; r++) ts[r * H_SZ + tid] = fast_tanh(acc[r]);
    __syncthreads();

    if (tid < 128) {
        int r = tid >> 4, kk = tid & 15;
        float l = gb2[kk];
#pragma unroll 4
        for (int i = 0; i < H_SZ; i++)
            l = fmaf(ts[r * H_SZ + i], gw2[i * K_SZ + kk], l);
        float m = l;
#pragma unroll
        for (int o = 8; o > 0; o >>= 1)
            m = fmaxf(m, __shfl_xor_sync(0xffffffffu, m, o));
        float e = __expf(l - m);
        float s = e;
#pragma unroll
        for (int o = 8; o > 0; o >>= 1)
            s += __shfl_xor_sync(0xffffffffu, s, o);
        g_gates[(b0 + r) * K_SZ + kk] = e / s;
    }
}

// ---------------------------------------------------------------------------
// Expert GEMM via mma.sync bf16 (3-term hi/lo split).
// Grid (64, 16): CTA = 64 batch rows x full 512 cols x 1 expert.
// 8 warps, each 64m x 64n. Double-buffered cp.async for B; A generated.
// ---------------------------------------------------------------------------
__device__ __forceinline__ void cp_B(int c, int k, uint32_t stage_base) {
    const int tid = threadIdx.x;
    const __nv_bfloat16* srch = g_Bhi + ((size_t)(k * D_SZ + c * BK)) * D_SZ;
    const __nv_bfloat16* srcl = g_Blo + ((size_t)(k * D_SZ + c * BK)) * D_SZ;
    uint32_t bhi = stage_base + 2 * A_MAT_BYTES;
    uint32_t blo = bhi + B_MAT_BYTES;
#pragma unroll
    for (int i = 0; i < 8; i++) {
        int idx = tid + i * 256;
        int row = idx >> 6, c8 = idx & 63;
        cp16(bhi + row * (SB * 2) + c8 * 16, srch + (size_t)row * D_SZ + c8 * 8);
        cp16(blo + row * (SB * 2) + c8 * 16, srcl + (size_t)row * D_SZ + c8 * 8);
    }
}

__device__ __forceinline__ void gen_A(int c, uint32_t stage_base,
                                      const float* s_x, const float* s_w1,
                                      const float* s_b1) {
    const int tid = threadIdx.x;
    const int m = tid >> 2, d0 = (tid & 3) * 8;
    const float xv = s_x[m];
    union { __nv_bfloat16 h[8]; uint4 u; } H, L;
#pragma unroll
    for (int j = 0; j < 8; j++) {
        int d = c * BK + d0 + j;
        float t = fast_tanh(fmaf(xv, s_w1[d], s_b1[d]));
        __nv_bfloat16 hi = __float2bfloat16(t);
        H.h[j] = hi;
        L.h[j] = __float2bfloat16(t - __bfloat162float(hi));
    }
    uint32_t off = (uint32_t)(m * (SA * 2) + d0 * 2);
    asm volatile("st.shared.v4.b32 [%0], {%1,%2,%3,%4};"
                 :: "r"(stage_base + off), "r"(H.u.x), "r"(H.u.y), "r"(H.u.z), "r"(H.u.w));
    asm volatile("st.shared.v4.b32 [%0], {%1,%2,%3,%4};"
                 :: "r"(stage_base + A_MAT_BYTES + off),
                    "r"(L.u.x), "r"(L.u.y), "r"(L.u.z), "r"(L.u.w));
}

__global__ void __launch_bounds__(256, 1)
expert_gemm_kernel(const float* __restrict__ x_ext, const float* __restrict__ w1,
                   const float* __restrict__ b1, const float* __restrict__ b2) {
    extern __shared__ __align__(128) char sm[];
    __shared__ float s_x[BM], s_w1[D_SZ], s_b1[D_SZ], s_b2[D_SZ];
    __shared__ float s_sum[BM], s_sq[BM];

    const int tid = threadIdx.x, wid = tid >> 5, lane = tid & 31;
    const int b0 = blockIdx.x * BM, k = blockIdx.y;
    const int wn = wid * 64;
    const uint32_t smb = smem_u32(sm);

    if (tid < BM) {
        s_x[tid] = x_ext[(b0 + tid) * K_SZ + k];
        s_sum[tid] = 0.0f;
        s_sq[tid] = 0.0f;
    }
    for (int i = tid; i < D_SZ; i += 256) {
        s_w1[i] = w1[k * D_SZ + i];
        s_b1[i] = b1[k * D_SZ + i];
        s_b2[i] = b2[k * D_SZ + i];
    }
    __syncthreads();

    // lane-derived fragment coordinates
    const int row16 = (lane & 7) + ((lane >> 3) & 1) * 8;  // A/B row within 16
    const int seg8  = ((lane >> 4) & 1) * 8;               // second 8-col/row half

    float acc[4][8][4];
#pragma unroll
    for (int a = 0; a < 4; a++)
#pragma unroll
        for (int b = 0; b < 8; b++)
#pragma unroll
            for (int q = 0; q < 4; q++) acc[a][b][q] = 0.0f;

    // prologue
    gen_A(0, smb, s_x, s_w1, s_b1);
    cp_B(0, k, smb);
    asm volatile("cp.async.commit_group;");

    for (int c = 0; c < D_SZ / BK; c++) {
        const uint32_t st = smb + (uint32_t)(c & 1) * STAGE_BYTES;
        const uint32_t nst = smb + (uint32_t)((c + 1) & 1) * STAGE_BYTES;
        asm volatile("cp.async.wait_group 0;" ::: "memory");
        __syncthreads();

        if (c + 1 < D_SZ / BK) {
            cp_B(c + 1, k, nst);
            asm volatile("cp.async.commit_group;");
        }

        const uint32_t Ahi = st, Alo = st + A_MAT_BYTES;
        const uint32_t Bhi = st + 2 * A_MAT_BYTES, Blo = Bhi + B_MAT_BYTES;

#pragma unroll
        for (int kk = 0; kk < 2; kk++) {
            uint32_t ah[4][4], al[4][4];
#pragma unroll
            for (int mb = 0; mb < 4; mb++) {
                uint32_t ao = (uint32_t)((mb * 16 + row16) * (SA * 2) +
                                         (kk * 16 + seg8) * 2);
                ldsm4(ah[mb], Ahi + ao);
                ldsm4(al[mb], Alo + ao);
            }
#pragma unroll
            for (int p = 0; p < 4; p++) {
                uint32_t bo = (uint32_t)((kk * 16 + row16) * (SB * 2) +
                                         (wn + p * 16 + seg8) * 2);
                uint32_t bh[4], bl[4];
                ldsm4t(bh, Bhi + bo);
                ldsm4t(bl, Blo + bo);
#pragma unroll
                for (int mb = 0; mb < 4; mb++) {
                    mma16816(acc[mb][2 * p],     ah[mb], bh[0], bh[1]);
                    mma16816(acc[mb][2 * p + 1], ah[mb], bh[2], bh[3]);
                    mma16816(acc[mb][2 * p],     ah[mb], bl[0], bl[1]);
                    mma16816(acc[mb][2 * p + 1], ah[mb], bl[2], bl[3]);
                    mma16816(acc[mb][2 * p],     al[mb], bh[0], bh[1]);
                    mma16816(acc[mb][2 * p + 1], al[mb], bh[2], bh[3]);
                }
            }
        }

        if (c + 1 < D_SZ / BK)
            gen_A(c + 1, nst, s_x, s_w1, s_b1);  // MUFU overlaps tensor drain
    }

    // Epilogue: +b2, tanh, store to g_raw, LN stats.
    {
        const int q = lane >> 2;
        const int c2 = (lane & 3) * 2;
        float ps[4][2], pq[4][2];
#pragma unroll
        for (int mb = 0; mb < 4; mb++) {
            ps[mb][0] = ps[mb][1] = 0.0f;
            pq[mb][0] = pq[mb][1] = 0.0f;
        }
#pragma unroll
        for (int mb = 0; mb < 4; mb++) {
            const int r0 = mb * 16 + q;
            float* o0 = &g_raw[((size_t)(b0 + r0) * K_SZ + k) * D_SZ];
            float* o1 = &g_raw[((size_t)(b0 + r0 + 8) * K_SZ + k) * D_SZ];
#pragma unroll
            for (int nb = 0; nb < 8; nb++) {
                const int e = wn + nb * 8 + c2;
                float bb0 = s_b2[e], bb1 = s_b2[e + 1];
                float v0 = fast_tanh(acc[mb][nb][0] + bb0);
                float v1 = fast_tanh(acc[mb][nb][1] + bb1);
                float v2 = fast_tanh(acc[mb][nb][2] + bb0);
                float v3 = fast_tanh(acc[mb][nb][3] + bb1);
                *(float2*)(o0 + e) = make_float2(v0, v1);
                *(float2*)(o1 + e) = make_float2(v2, v3);
                ps[mb][0] += v0 + v1;
                ps[mb][1] += v2 + v3;
                pq[mb][0] += v0 * v0 + v1 * v1;
                pq[mb][1] += v2 * v2 + v3 * v3;
            }
        }
#pragma unroll
        for (int mb = 0; mb < 4; mb++) {
            atomicAdd(&s_sum[mb * 16 + q], ps[mb][0]);
            atomicAdd(&s_sq[mb * 16 + q], pq[mb][0]);
            atomicAdd(&s_sum[mb * 16 + q + 8], ps[mb][1]);
            atomicAdd(&s_sq[mb * 16 + q + 8], pq[mb][1]);
        }
    }
    __syncthreads();
    if (tid < BM) {
        float mu  = s_sum[tid] * (1.0f / (float)D_SZ);
        float var = s_sq[tid] * (1.0f / (float)D_SZ) - mu * mu;
        g_mean[(b0 + tid) * K_SZ + k] = mu;
        g_rstd[(b0 + tid) * K_SZ + k] = rsqrtf(var + LN_EPS);
    }
}

// ---------------------------------------------------------------------------
// Combine: theta_e = ln_g*(sum_k a_k*v - c) + ln_b + th0 ; then x_prime.
// a_k = gate_k*rstd_k, c = sum_k a_k*mean_k. (softmax gates sum to 1)
// ---------------------------------------------------------------------------
__global__ void __launch_bounds__(256) combine_kernel(
    const float* __restrict__ x_l, const float* __restrict__ ln_g,
    const float* __restrict__ ln_b, const float* __restrict__ theta0,
    float* __restrict__ out) {
    __shared__ float s_a[K_SZ], s_am[K_SZ];
    __shared__ float th[D_SZ];
    const int b = blockIdx.x;
    const int tid = threadIdx.x;

    if (tid < K_SZ) {
        float g  = g_gates[b * K_SZ + tid];
        float rs = g_rstd[b * K_SZ + tid];
        float a  = g * rs;
        s_a[tid]  = a;
        s_am[tid] = a * g_mean[b * K_SZ + tid];
    }
    __syncthreads();

    float cc = 0.0f;
#pragma unroll
    for (int kk = 0; kk < K_SZ; kk++) cc += s_am[kk];

    const float* rawb = &g_raw[(size_t)b * K_SZ * D_SZ];
#pragma unroll
    for (int e = tid; e < D_SZ; e += 256) {
        float acc = 0.0f;
#pragma unroll
        for (int kk = 0; kk < K_SZ; kk++)
            acc = fmaf(s_a[kk], __ldcs(&rawb[kk * D_SZ + e]), acc);
        float t = fmaf(ln_g[e], acc - cc, ln_b[e]) + theta0[e];
        th[e] = t;
        out[(size_t)B_SZ * XP_DIM + (size_t)b * D_SZ + e] = t;
    }
    __syncthreads();

    if (tid < XP_DIM) {
        float xp = 0.0f;
#pragma unroll
        for (int i = 0; i < IN_DIM; i++)
            xp = fmaf(x_l[b * IN_DIM + i], th[i * XP_DIM + tid], xp);
        out[b * XP_DIM + tid] = xp;
    }
}

// ---------------------------------------------------------------------------
extern "C" void kernel_launch(void* const* d_in, const int* in_sizes, int n_in,
                              void* d_out, int out_size) {
    const float* h_prev = (const float*)d_in[0];
    const float* x_l    = (const float*)d_in[1];
    const float* x_ext  = (const float*)d_in[2];
    const float* w1     = (const float*)d_in[3];
    const float* b1     = (const float*)d_in[4];
    const float* w2     = (const float*)d_in[5];
    const float* b2     = (const float*)d_in[6];
    const float* gw1    = (const float*)d_in[7];
    const float* gb1    = (const float*)d_in[8];
    const float* gw2    = (const float*)d_in[9];
    const float* gb2    = (const float*)d_in[10];
    const float* ln_g   = (const float*)d_in[11];
    const float* ln_b   = (const float*)d_in[12];
    const float* th0    = (const float*)d_in[13];
    float* out = (float*)d_out;

    cudaFuncSetAttribute(expert_gemm_kernel,
                         cudaFuncAttributeMaxDynamicSharedMemorySize, GEMM_SMEM);

    prep_kernel<<<(K_SZ * D_SZ * D_SZ) / (256 * 8), 256>>>(w2);
    gating_kernel<<<B_SZ / 8, 256>>>(h_prev, gw1, gb1, gw2, gb2);
    expert_gemm_kernel<<<dim3(B_SZ / BM, K_SZ), 256, GEMM_SMEM>>>(x_ext, w1, b1, b2);
    combine_kernel<<<B_SZ, 256>>>(x_l, ln_g, ln_b, th0, out);
}

// round 4
// speedup vs baseline: 4.5267x; 1.2875x over previous
#include <cuda_runtime.h>
#include <cuda_fp16.h>
#include <math.h>
#include <stdint.h>

#define B_SZ   4096
#define H_SZ   256
#define K_SZ   16
#define D_SZ   512
#define IN_DIM 8
#define XP_DIM 64
#define LN_EPS 1e-5f

// GEMM tiling: CTA = 128 rows x 256 cols x 1 expert, 8 warps (2m x 4n), 64x64 each
#define BM 128
#define BN 256
#define BK 32
#define SA 40                     // A smem row stride (halves)
#define SB 264                    // B smem row stride (halves)
#define A_BYTES (BM * SA * 2)     // 10240
#define B_BYTES (BK * SB * 2)     // 16896
#define STAGE (A_BYTES + 2 * B_BYTES)  // 44032
#define NSTAGE 3
#define GEMM_SMEM (NSTAGE * STAGE)     // 132096

// ---------------- scratch -----------------------------------------------
__device__ __half g_raw[(size_t)B_SZ * K_SZ * D_SZ];        // post-tanh h2 (64MB)
__device__ float  g_psum[2][B_SZ * K_SZ];                   // per-N-half LN partials
__device__ float  g_psq[2][B_SZ * K_SZ];
__device__ float  g_gates[B_SZ * K_SZ];
__device__ __half g_Bhi[(size_t)K_SZ * D_SZ * D_SZ];        // 16*w2 hi, [k][d][e]
__device__ __half g_Blo[(size_t)K_SZ * D_SZ * D_SZ];        // 16*w2 lo

// ---------------- helpers ------------------------------------------------
__device__ __forceinline__ float fast_tanh(float x) {
    float e = __expf(2.0f * x);
    return 1.0f - __fdividef(2.0f, e + 1.0f);
}

__device__ __forceinline__ uint32_t smem_u32(const void* p) {
    uint32_t a;
    asm("{ .reg .u64 t; cvta.to.shared.u64 t, %1; cvt.u32.u64 %0, t; }"
        : "=r"(a) : "l"(p));
    return a;
}

__device__ __forceinline__ void cp16(uint32_t dst, const void* src) {
    asm volatile("cp.async.cg.shared.global [%0], [%1], 16;" :: "r"(dst), "l"(src));
}

__device__ __forceinline__ void ldsm4(uint32_t* r, uint32_t a) {
    asm volatile("ldmatrix.sync.aligned.m8n8.x4.shared.b16 {%0,%1,%2,%3}, [%4];"
                 : "=r"(r[0]), "=r"(r[1]), "=r"(r[2]), "=r"(r[3]) : "r"(a));
}

__device__ __forceinline__ void ldsm4t(uint32_t* r, uint32_t a) {
    asm volatile("ldmatrix.sync.aligned.m8n8.x4.trans.shared.b16 {%0,%1,%2,%3}, [%4];"
                 : "=r"(r[0]), "=r"(r[1]), "=r"(r[2]), "=r"(r[3]) : "r"(a));
}

__device__ __forceinline__ void mma16816(float* c, const uint32_t* a,
                                         uint32_t b0, uint32_t b1) {
    asm volatile(
        "mma.sync.aligned.m16n8k16.row.col.f32.f16.f16.f32 "
        "{%0,%1,%2,%3}, {%4,%5,%6,%7}, {%8,%9}, {%0,%1,%2,%3};"
        : "+f"(c[0]), "+f"(c[1]), "+f"(c[2]), "+f"(c[3])
        : "r"(a[0]), "r"(a[1]), "r"(a[2]), "r"(a[3]), "r"(b0), "r"(b1));
}

// ---------------------------------------------------------------------------
// Prep: 16*w2 fp32 -> hi/lo fp16, [k][d][e] layout. 2048 blocks x 256 thr.
// ---------------------------------------------------------------------------
__global__ void __launch_bounds__(256) prep_kernel(const float* __restrict__ w2) {
    size_t idx = ((size_t)blockIdx.x * 256 + threadIdx.x) * 8;
    float4 v0 = *(const float4*)(w2 + idx);
    float4 v1 = *(const float4*)(w2 + idx + 4);
    float v[8] = {v0.x, v0.y, v0.z, v0.w, v1.x, v1.y, v1.z, v1.w};
    union { __half h[8]; uint4 u; } H, L;
#pragma unroll
    for (int j = 0; j < 8; j++) {
        float s = v[j] * 16.0f;
        __half hi = __float2half_rn(s);
        H.h[j] = hi;
        L.h[j] = __float2half_rn(s - __half2float(hi));
    }
    *(uint4*)(g_Bhi + idx) = H.u;
    *(uint4*)(g_Blo + idx) = L.u;
}

// ---------------------------------------------------------------------------
// Gating: 8 batch rows per block.
// ---------------------------------------------------------------------------
__global__ void __launch_bounds__(256) gating_kernel(
    const float* __restrict__ h_prev, const float* __restrict__ gw1,
    const float* __restrict__ gb1, const float* __restrict__ gw2,
    const float* __restrict__ gb2) {
    __shared__ float hsT[H_SZ * 8];
    __shared__ float ts[8 * H_SZ];
    const int b0 = blockIdx.x * 8;
    const int tid = threadIdx.x;

    for (int idx = tid; idx < 8 * H_SZ; idx += 256) {
        int r = idx >> 8, i = idx & 255;
        hsT[i * 8 + r] = h_prev[(b0 + r) * H_SZ + i];
    }
    __syncthreads();

    float acc[8];
    {
        float bb = gb1[tid];
#pragma unroll
        for (int r = 0; r < 8; r++) acc[r] = bb;
    }
#pragma unroll 4
    for (int i = 0; i < H_SZ; i++) {
        float w = gw1[i * H_SZ + tid];
        float4 a0 = *(const float4*)&hsT[i * 8];
        float4 a1 = *(const float4*)&hsT[i * 8 + 4];
        acc[0] = fmaf(a0.x, w, acc[0]);
        acc[1] = fmaf(a0.y, w, acc[1]);
        acc[2] = fmaf(a0.z, w, acc[2]);
        acc[3] = fmaf(a0.w, w, acc[3]);
        acc[4] = fmaf(a1.x, w, acc[4]);
        acc[5] = fmaf(a1.y, w, acc[5]);
        acc[6] = fmaf(a1.z, w, acc[6]);
        acc[7] = fmaf(a1.w, w, acc[7]);
    }
#pragma unroll
    for (int r = 0; r < 8; r++) ts[r * H_SZ + tid] = fast_tanh(acc[r]);
    __syncthreads();

    if (tid < 128) {
        int r = tid >> 4, kk = tid & 15;
        float l = gb2[kk];
#pragma unroll 4
        for (int i = 0; i < H_SZ; i++)
            l = fmaf(ts[r * H_SZ + i], gw2[i * K_SZ + kk], l);
        float m = l;
#pragma unroll
        for (int o = 8; o > 0; o >>= 1)
            m = fmaxf(m, __shfl_xor_sync(0xffffffffu, m, o));
        float e = __expf(l - m);
        float s = e;
#pragma unroll
        for (int o = 8; o > 0; o >>= 1)
            s += __shfl_xor_sync(0xffffffffu, s, o);
        g_gates[(b0 + r) * K_SZ + kk] = e / s;
    }
}

// ---------------------------------------------------------------------------
// Expert GEMM, fp16 2-term split: acc = sum_d ahi*(bhi + blo), result = 16*true.
// Grid (32, 2, 16): (m-block, n-half, expert). 256 threads, 3-stage cp.async.
// ---------------------------------------------------------------------------
__device__ __forceinline__ void cp_B(int c, int k, int n0, uint32_t stage) {
    const int tid = threadIdx.x;
    const __half* srch = g_Bhi + ((size_t)(k * D_SZ + c * BK)) * D_SZ + n0;
    const __half* srcl = g_Blo + ((size_t)(k * D_SZ + c * BK)) * D_SZ + n0;
    uint32_t bhi = stage + A_BYTES;
    uint32_t blo = bhi + B_BYTES;
#pragma unroll
    for (int i = 0; i < 4; i++) {
        int idx = tid + i * 256;
        int row = idx >> 5, ch = idx & 31;
        cp16(bhi + row * (SB * 2) + ch * 16, srch + (size_t)row * D_SZ + ch * 8);
        cp16(blo + row * (SB * 2) + ch * 16, srcl + (size_t)row * D_SZ + ch * 8);
    }
}

__device__ __forceinline__ void gen_A(int c, uint32_t stage, const float* s_x,
                                      const float* s_w1, const float* s_b1) {
    const int tid = threadIdx.x;
#pragma unroll
    for (int it = 0; it < 2; it++) {
        int u = tid + it * 256;
        int m = u >> 2, d0 = (u & 3) * 8;
        float xv = s_x[m];
        union { __half h[8]; uint4 v; } H;
#pragma unroll
        for (int j = 0; j < 8; j++) {
            int d = c * BK + d0 + j;
            H.h[j] = __float2half_rn(fast_tanh(fmaf(xv, s_w1[d], s_b1[d])));
        }
        asm volatile("st.shared.v4.b32 [%0], {%1,%2,%3,%4};"
                     :: "r"(stage + (uint32_t)(m * (SA * 2) + d0 * 2)),
                        "r"(H.v.x), "r"(H.v.y), "r"(H.v.z), "r"(H.v.w));
    }
}

__global__ void __launch_bounds__(256, 1)
expert_gemm_kernel(const float* __restrict__ x_ext, const float* __restrict__ w1,
                   const float* __restrict__ b1, const float* __restrict__ b2) {
    extern __shared__ __align__(128) char sm[];
    __shared__ float s_x[BM], s_w1[D_SZ], s_b1[D_SZ], s_b2[BN];
    __shared__ float s_sum[BM], s_sq[BM];

    const int tid = threadIdx.x, wid = tid >> 5, lane = tid & 31;
    const int b0 = blockIdx.x * BM, ny = blockIdx.y, k = blockIdx.z;
    const int n0 = ny * BN;
    const int wm = (wid >> 2) * 64, wn = (wid & 3) * 64;
    const uint32_t smb = smem_u32(sm);

    if (tid < BM) {
        s_x[tid] = x_ext[(b0 + tid) * K_SZ + k];
        s_sum[tid] = 0.0f;
        s_sq[tid] = 0.0f;
    }
    for (int i = tid; i < D_SZ; i += 256) {
        s_w1[i] = w1[k * D_SZ + i];
        s_b1[i] = b1[k * D_SZ + i];
    }
    if (tid < BN) s_b2[tid] = b2[k * D_SZ + n0 + tid];
    __syncthreads();

    const int row16 = (lane & 7) + ((lane >> 3) & 1) * 8;
    const int seg8  = ((lane >> 4) & 1) * 8;

    float acc[4][8][4];
#pragma unroll
    for (int a = 0; a < 4; a++)
#pragma unroll
        for (int b = 0; b < 8; b++)
#pragma unroll
            for (int q = 0; q < 4; q++) acc[a][b][q] = 0.0f;

    // prologue: stages 0,1
    cp_B(0, k, n0, smb);
    asm volatile("cp.async.commit_group;");
    cp_B(1, k, n0, smb + STAGE);
    asm volatile("cp.async.commit_group;");
    gen_A(0, smb, s_x, s_w1, s_b1);
    gen_A(1, smb + STAGE, s_x, s_w1, s_b1);

    for (int c = 0; c < D_SZ / BK; c++) {
        const uint32_t st = smb + (uint32_t)(c % NSTAGE) * STAGE;
        if (c < 14)
            asm volatile("cp.async.wait_group 1;" ::: "memory");
        else
            asm volatile("cp.async.wait_group 0;" ::: "memory");
        __syncthreads();

        if (c + 2 < D_SZ / BK) {
            const uint32_t nst = smb + (uint32_t)((c + 2) % NSTAGE) * STAGE;
            cp_B(c + 2, k, n0, nst);
            asm volatile("cp.async.commit_group;");
        }

        const uint32_t As = st, Bh = st + A_BYTES, Bl = Bh + B_BYTES;
#pragma unroll
        for (int kk = 0; kk < 2; kk++) {
            uint32_t ah[4][4];
#pragma unroll
            for (int mb = 0; mb < 4; mb++)
                ldsm4(ah[mb], As + (uint32_t)((wm + mb * 16 + row16) * (SA * 2) +
                                              (kk * 16 + seg8) * 2));
#pragma unroll
            for (int p = 0; p < 4; p++) {
                uint32_t bo = (uint32_t)((kk * 16 + row16) * (SB * 2) +
                                         (wn + p * 16 + seg8) * 2);
                uint32_t bh[4], bl[4];
                ldsm4t(bh, Bh + bo);
                ldsm4t(bl, Bl + bo);
#pragma unroll
                for (int mb = 0; mb < 4; mb++) {
                    mma16816(acc[mb][2 * p],     ah[mb], bh[0], bh[1]);
                    mma16816(acc[mb][2 * p + 1], ah[mb], bh[2], bh[3]);
                    mma16816(acc[mb][2 * p],     ah[mb], bl[0], bl[1]);
                    mma16816(acc[mb][2 * p + 1], ah[mb], bl[2], bl[3]);
                }
            }
        }

        if (c + 2 < D_SZ / BK) {
            const uint32_t nst = smb + (uint32_t)((c + 2) % NSTAGE) * STAGE;
            gen_A(c + 2, nst, s_x, s_w1, s_b1);   // MUFU overlaps tensor drain
        }
    }

    // Epilogue: v = tanh(acc/16 + b2); fp16 store; LN partial stats.
    {
        const int q = lane >> 2, c2 = (lane & 3) * 2;
#pragma unroll
        for (int mb = 0; mb < 4; mb++) {
            const int r0 = wm + mb * 16 + q;
            __half* o0 = &g_raw[((size_t)(b0 + r0) * K_SZ + k) * D_SZ + n0];
            __half* o1 = &g_raw[((size_t)(b0 + r0 + 8) * K_SZ + k) * D_SZ + n0];
            float ps0 = 0.f, ps1 = 0.f, pq0 = 0.f, pq1 = 0.f;
#pragma unroll
            for (int nb = 0; nb < 8; nb++) {
                const int e = wn + nb * 8 + c2;
                float bb0 = s_b2[e], bb1 = s_b2[e + 1];
                float v0 = fast_tanh(fmaf(acc[mb][nb][0], 0.0625f, bb0));
                float v1 = fast_tanh(fmaf(acc[mb][nb][1], 0.0625f, bb1));
                float v2 = fast_tanh(fmaf(acc[mb][nb][2], 0.0625f, bb0));
                float v3 = fast_tanh(fmaf(acc[mb][nb][3], 0.0625f, bb1));
                *(__half2*)(o0 + e) = __floats2half2_rn(v0, v1);
                *(__half2*)(o1 + e) = __floats2half2_rn(v2, v3);
                ps0 += v0 + v1; ps1 += v2 + v3;
                pq0 += v0 * v0 + v1 * v1; pq1 += v2 * v2 + v3 * v3;
            }
            atomicAdd(&s_sum[r0], ps0);
            atomicAdd(&s_sq[r0], pq0);
            atomicAdd(&s_sum[r0 + 8], ps1);
            atomicAdd(&s_sq[r0 + 8], pq1);
        }
    }
    __syncthreads();
    if (tid < BM) {
        g_psum[ny][(b0 + tid) * K_SZ + k] = s_sum[tid];
        g_psq[ny][(b0 + tid) * K_SZ + k] = s_sq[tid];
    }
}

// ---------------------------------------------------------------------------
// Combine: theta_e = ln_g*(sum_k a_k*v - c) + ln_b + th0 ; then x_prime.
// ---------------------------------------------------------------------------
__global__ void __launch_bounds__(256) combine_kernel(
    const float* __restrict__ x_l, const float* __restrict__ ln_g,
    const float* __restrict__ ln_b, const float* __restrict__ theta0,
    float* __restrict__ out) {
    __shared__ float s_a[K_SZ], s_am[K_SZ];
    __shared__ float th[D_SZ];
    const int b = blockIdx.x;
    const int tid = threadIdx.x;

    if (tid < K_SZ) {
        int idx = b * K_SZ + tid;
        float su = g_psum[0][idx] + g_psum[1][idx];
        float sq = g_psq[0][idx] + g_psq[1][idx];
        float mu = su * (1.0f / (float)D_SZ);
        float var = sq * (1.0f / (float)D_SZ) - mu * mu;
        float rs = rsqrtf(var + LN_EPS);
        float a = g_gates[idx] * rs;
        s_a[tid] = a;
        s_am[tid] = a * mu;
    }
    __syncthreads();

    float cc = 0.0f;
#pragma unroll
    for (int kk = 0; kk < K_SZ; kk++) cc += s_am[kk];

    const __half* rawb = &g_raw[(size_t)b * K_SZ * D_SZ];
#pragma unroll
    for (int e = tid; e < D_SZ; e += 256) {
        float acc = 0.0f;
#pragma unroll
        for (int kk = 0; kk < K_SZ; kk++)
            acc = fmaf(s_a[kk], __half2float(rawb[kk * D_SZ + e]), acc);
        float t = fmaf(ln_g[e], acc - cc, ln_b[e]) + theta0[e];
        th[e] = t;
        out[(size_t)B_SZ * XP_DIM + (size_t)b * D_SZ + e] = t;
    }
    __syncthreads();

    if (tid < XP_DIM) {
        float xp = 0.0f;
#pragma unroll
        for (int i = 0; i < IN_DIM; i++)
            xp = fmaf(x_l[b * IN_DIM + i], th[i * XP_DIM + tid], xp);
        out[b * XP_DIM + tid] = xp;
    }
}

// ---------------------------------------------------------------------------
extern "C" void kernel_launch(void* const* d_in, const int* in_sizes, int n_in,
                              void* d_out, int out_size) {
    const float* h_prev = (const float*)d_in[0];
    const float* x_l    = (const float*)d_in[1];
    const float* x_ext  = (const float*)d_in[2];
    const float* w1     = (const float*)d_in[3];
    const float* b1     = (const float*)d_in[4];
    const float* w2     = (const float*)d_in[5];
    const float* b2     = (const float*)d_in[6];
    const float* gw1    = (const float*)d_in[7];
    const float* gb1    = (const float*)d_in[8];
    const float* gw2    = (const float*)d_in[9];
    const float* gb2    = (const float*)d_in[10];
    const float* ln_g   = (const float*)d_in[11];
    const float* ln_b   = (const float*)d_in[12];
    const float* th0    = (const float*)d_in[13];
    float* out = (float*)d_out;

    cudaFuncSetAttribute(expert_gemm_kernel,
                         cudaFuncAttributeMaxDynamicSharedMemorySize, GEMM_SMEM);

    prep_kernel<<<(K_SZ * D_SZ * D_SZ) / (256 * 8), 256>>>(w2);
    gating_kernel<<<B_SZ / 8, 256>>>(h_prev, gw1, gb1, gw2, gb2);
    expert_gemm_kernel<<<dim3(B_SZ / BM, 2, K_SZ), 256, GEMM_SMEM>>>(x_ext, w1, b1, b2);
    combine_kernel<<<B_SZ, 256>>>(x_l, ln_g, ln_b, th0, out);
}

// round 5
// speedup vs baseline: 5.9474x; 1.3139x over previous
#include <cuda_runtime.h>
#include <cuda_fp16.h>
#include <math.h>
#include <stdint.h>

#define B_SZ   4096
#define H_SZ   256
#define K_SZ   16
#define D_SZ   512
#define IN_DIM 8
#define XP_DIM 64
#define LN_EPS 1e-5f

// GEMM tiling: CTA = 128 rows x 256 cols x 1 expert, 8 warps (2m x 4n), 64x64 each
#define BM 128
#define BN 256
#define BK 32
#define SA 40                     // A smem row stride (halves)
#define SB 264                    // B smem row stride (halves)
#define A_BYTES (BM * SA * 2)     // 10240
#define B_BYTES (BK * SB * 2)     // 16896
#define STAGE (A_BYTES + B_BYTES) // 27136
#define NSTAGE 4
#define GEMM_SMEM (NSTAGE * STAGE)  // 108544

// ---------------- scratch -----------------------------------------------
__device__ __half g_raw[(size_t)B_SZ * K_SZ * D_SZ];        // post-tanh h2 (64MB)
__device__ float  g_psum[2][B_SZ * K_SZ];                   // per-N-half LN partials
__device__ float  g_psq[2][B_SZ * K_SZ];
__device__ float  g_gates[B_SZ * K_SZ];
__device__ __half g_Bhi[(size_t)K_SZ * D_SZ * D_SZ];        // 16*w2 fp16, [k][d][e]

// ---------------- helpers ------------------------------------------------
__device__ __forceinline__ float fast_tanh(float x) {
    float e = __expf(2.0f * x);
    return 1.0f - __fdividef(2.0f, e + 1.0f);
}

__device__ __forceinline__ uint32_t smem_u32(const void* p) {
    uint32_t a;
    asm("{ .reg .u64 t; cvta.to.shared.u64 t, %1; cvt.u32.u64 %0, t; }"
        : "=r"(a) : "l"(p));
    return a;
}

__device__ __forceinline__ void cp16(uint32_t dst, const void* src) {
    asm volatile("cp.async.cg.shared.global [%0], [%1], 16;" :: "r"(dst), "l"(src));
}

__device__ __forceinline__ void ldsm4(uint32_t* r, uint32_t a) {
    asm volatile("ldmatrix.sync.aligned.m8n8.x4.shared.b16 {%0,%1,%2,%3}, [%4];"
                 : "=r"(r[0]), "=r"(r[1]), "=r"(r[2]), "=r"(r[3]) : "r"(a));
}

__device__ __forceinline__ void ldsm4t(uint32_t* r, uint32_t a) {
    asm volatile("ldmatrix.sync.aligned.m8n8.x4.trans.shared.b16 {%0,%1,%2,%3}, [%4];"
                 : "=r"(r[0]), "=r"(r[1]), "=r"(r[2]), "=r"(r[3]) : "r"(a));
}

__device__ __forceinline__ void mma16816(float* c, const uint32_t* a,
                                         uint32_t b0, uint32_t b1) {
    asm volatile(
        "mma.sync.aligned.m16n8k16.row.col.f32.f16.f16.f32 "
        "{%0,%1,%2,%3}, {%4,%5,%6,%7}, {%8,%9}, {%0,%1,%2,%3};"
        : "+f"(c[0]), "+f"(c[1]), "+f"(c[2]), "+f"(c[3])
        : "r"(a[0]), "r"(a[1]), "r"(a[2]), "r"(a[3]), "r"(b0), "r"(b1));
}

// ---------------------------------------------------------------------------
// Fused prep (blocks 0..2047) + gating (blocks 2048..2559).
// prep: 16*w2 fp32 -> fp16, [k][d][e]. gating: 8 batch rows per block.
// ---------------------------------------------------------------------------
__global__ void __launch_bounds__(256) prep_gating_kernel(
    const float* __restrict__ w2,
    const float* __restrict__ h_prev, const float* __restrict__ gw1,
    const float* __restrict__ gb1, const float* __restrict__ gw2,
    const float* __restrict__ gb2) {
    const int tid = threadIdx.x;

    if (blockIdx.x < 2048) {
        size_t idx = ((size_t)blockIdx.x * 256 + tid) * 8;
        float4 v0 = *(const float4*)(w2 + idx);
        float4 v1 = *(const float4*)(w2 + idx + 4);
        float v[8] = {v0.x, v0.y, v0.z, v0.w, v1.x, v1.y, v1.z, v1.w};
        union { __half h[8]; uint4 u; } H;
#pragma unroll
        for (int j = 0; j < 8; j++)
            H.h[j] = __float2half_rn(v[j] * 16.0f);
        *(uint4*)(g_Bhi + idx) = H.u;
        return;
    }

    __shared__ float hsT[H_SZ * 8];
    __shared__ float ts[8 * H_SZ];
    const int b0 = (blockIdx.x - 2048) * 8;

    for (int idx = tid; idx < 8 * H_SZ; idx += 256) {
        int r = idx >> 8, i = idx & 255;
        hsT[i * 8 + r] = h_prev[(b0 + r) * H_SZ + i];
    }
    __syncthreads();

    float acc[8];
    {
        float bb = gb1[tid];
#pragma unroll
        for (int r = 0; r < 8; r++) acc[r] = bb;
    }
#pragma unroll 4
    for (int i = 0; i < H_SZ; i++) {
        float w = gw1[i * H_SZ + tid];
        float4 a0 = *(const float4*)&hsT[i * 8];
        float4 a1 = *(const float4*)&hsT[i * 8 + 4];
        acc[0] = fmaf(a0.x, w, acc[0]);
        acc[1] = fmaf(a0.y, w, acc[1]);
        acc[2] = fmaf(a0.z, w, acc[2]);
        acc[3] = fmaf(a0.w, w, acc[3]);
        acc[4] = fmaf(a1.x, w, acc[4]);
        acc[5] = fmaf(a1.y, w, acc[5]);
        acc[6] = fmaf(a1.z, w, acc[6]);
        acc[7] = fmaf(a1.w, w, acc[7]);
    }
#pragma unroll
    for (int r = 0; r < 8; r++) ts[r * H_SZ + tid] = fast_tanh(acc[r]);
    __syncthreads();

    if (tid < 128) {
        int r = tid >> 4, kk = tid & 15;
        float l = gb2[kk];
#pragma unroll 4
        for (int i = 0; i < H_SZ; i++)
            l = fmaf(ts[r * H_SZ + i], gw2[i * K_SZ + kk], l);
        float m = l;
#pragma unroll
        for (int o = 8; o > 0; o >>= 1)
            m = fmaxf(m, __shfl_xor_sync(0xffffffffu, m, o));
        float e = __expf(l - m);
        float s = e;
#pragma unroll
        for (int o = 8; o > 0; o >>= 1)
            s += __shfl_xor_sync(0xffffffffu, s, o);
        g_gates[(b0 + r) * K_SZ + kk] = e / s;
    }
}

// ---------------------------------------------------------------------------
// Expert GEMM, fp16 1-term: acc = sum_d ahi*bhi, result = 16*true.
// Grid (32, 2, 16): (m-block, n-half, expert). 256 threads, 4-stage cp.async.
// ---------------------------------------------------------------------------
__device__ __forceinline__ void cp_B(int c, int k, int n0, uint32_t stage) {
    const int tid = threadIdx.x;
    const __half* srch = g_Bhi + ((size_t)(k * D_SZ + c * BK)) * D_SZ + n0;
    uint32_t bhi = stage + A_BYTES;
#pragma unroll
    for (int i = 0; i < 4; i++) {
        int idx = tid + i * 256;
        int row = idx >> 5, ch = idx & 31;
        cp16(bhi + row * (SB * 2) + ch * 16, srch + (size_t)row * D_SZ + ch * 8);
    }
}

__device__ __forceinline__ void gen_A(int c, uint32_t stage, const float* s_x,
                                      const float* s_w1, const float* s_b1) {
    const int tid = threadIdx.x;
#pragma unroll
    for (int it = 0; it < 2; it++) {
        int u = tid + it * 256;
        int m = u >> 2, d0 = (u & 3) * 8;
        float xv = s_x[m];
        union { __half h[8]; uint4 v; } H;
#pragma unroll
        for (int j = 0; j < 8; j++) {
            int d = c * BK + d0 + j;
            H.h[j] = __float2half_rn(fast_tanh(fmaf(xv, s_w1[d], s_b1[d])));
        }
        asm volatile("st.shared.v4.b32 [%0], {%1,%2,%3,%4};"
                     :: "r"(stage + (uint32_t)(m * (SA * 2) + d0 * 2)),
                        "r"(H.v.x), "r"(H.v.y), "r"(H.v.z), "r"(H.v.w));
    }
}

__global__ void __launch_bounds__(256, 1)
expert_gemm_kernel(const float* __restrict__ x_ext, const float* __restrict__ w1,
                   const float* __restrict__ b1, const float* __restrict__ b2) {
    extern __shared__ __align__(128) char sm[];
    __shared__ float s_x[BM], s_w1[D_SZ], s_b1[D_SZ], s_b2[BN];
    __shared__ float s_sum[BM], s_sq[BM];

    const int tid = threadIdx.x, wid = tid >> 5, lane = tid & 31;
    const int b0 = blockIdx.x * BM, ny = blockIdx.y, k = blockIdx.z;
    const int n0 = ny * BN;
    const int wm = (wid >> 2) * 64, wn = (wid & 3) * 64;
    const uint32_t smb = smem_u32(sm);

    if (tid < BM) {
        s_x[tid] = x_ext[(b0 + tid) * K_SZ + k];
        s_sum[tid] = 0.0f;
        s_sq[tid] = 0.0f;
    }
    for (int i = tid; i < D_SZ; i += 256) {
        s_w1[i] = w1[k * D_SZ + i];
        s_b1[i] = b1[k * D_SZ + i];
    }
    if (tid < BN) s_b2[tid] = b2[k * D_SZ + n0 + tid];
    __syncthreads();

    const int row16 = (lane & 7) + ((lane >> 3) & 1) * 8;
    const int seg8  = ((lane >> 4) & 1) * 8;

    float acc[4][8][4];
#pragma unroll
    for (int a = 0; a < 4; a++)
#pragma unroll
        for (int b = 0; b < 8; b++)
#pragma unroll
            for (int q = 0; q < 4; q++) acc[a][b][q] = 0.0f;

    // prologue: stages 0..2
#pragma unroll
    for (int s = 0; s < 3; s++) {
        cp_B(s, k, n0, smb + (uint32_t)s * STAGE);
        asm volatile("cp.async.commit_group;");
    }
#pragma unroll
    for (int s = 0; s < 3; s++)
        gen_A(s, smb + (uint32_t)s * STAGE, s_x, s_w1, s_b1);

    for (int c = 0; c < D_SZ / BK; c++) {
        const uint32_t st = smb + (uint32_t)(c & 3) * STAGE;
        if (c <= 13)
            asm volatile("cp.async.wait_group 2;" ::: "memory");
        else if (c == 14)
            asm volatile("cp.async.wait_group 1;" ::: "memory");
        else
            asm volatile("cp.async.wait_group 0;" ::: "memory");
        __syncthreads();

        if (c + 3 < D_SZ / BK) {
            const uint32_t nst = smb + (uint32_t)((c + 3) & 3) * STAGE;
            cp_B(c + 3, k, n0, nst);
            asm volatile("cp.async.commit_group;");
        }

        const uint32_t As = st, Bh = st + A_BYTES;
#pragma unroll
        for (int kk = 0; kk < 2; kk++) {
            uint32_t ah[4][4];
#pragma unroll
            for (int mb = 0; mb < 4; mb++)
                ldsm4(ah[mb], As + (uint32_t)((wm + mb * 16 + row16) * (SA * 2) +
                                              (kk * 16 + seg8) * 2));
#pragma unroll
            for (int p = 0; p < 4; p++) {
                uint32_t bh[4];
                ldsm4t(bh, Bh + (uint32_t)((kk * 16 + row16) * (SB * 2) +
                                           (wn + p * 16 + seg8) * 2));
#pragma unroll
                for (int mb = 0; mb < 4; mb++) {
                    mma16816(acc[mb][2 * p],     ah[mb], bh[0], bh[1]);
                    mma16816(acc[mb][2 * p + 1], ah[mb], bh[2], bh[3]);
                }
            }
        }

        if (c + 3 < D_SZ / BK) {
            const uint32_t nst = smb + (uint32_t)((c + 3) & 3) * STAGE;
            gen_A(c + 3, nst, s_x, s_w1, s_b1);   // MUFU overlaps tensor drain
        }
    }

    // Epilogue: v = tanh(acc/16 + b2); fp16 store; LN partial stats.
    {
        const int q = lane >> 2, c2 = (lane & 3) * 2;
#pragma unroll
        for (int mb = 0; mb < 4; mb++) {
            const int r0 = wm + mb * 16 + q;
            __half* o0 = &g_raw[((size_t)(b0 + r0) * K_SZ + k) * D_SZ + n0];
            __half* o1 = &g_raw[((size_t)(b0 + r0 + 8) * K_SZ + k) * D_SZ + n0];
            float ps0 = 0.f, ps1 = 0.f, pq0 = 0.f, pq1 = 0.f;
#pragma unroll
            for (int nb = 0; nb < 8; nb++) {
                const int e = wn + nb * 8 + c2;
                float bb0 = s_b2[e], bb1 = s_b2[e + 1];
                float v0 = fast_tanh(fmaf(acc[mb][nb][0], 0.0625f, bb0));
                float v1 = fast_tanh(fmaf(acc[mb][nb][1], 0.0625f, bb1));
                float v2 = fast_tanh(fmaf(acc[mb][nb][2], 0.0625f, bb0));
                float v3 = fast_tanh(fmaf(acc[mb][nb][3], 0.0625f, bb1));
                *(__half2*)(o0 + e) = __floats2half2_rn(v0, v1);
                *(__half2*)(o1 + e) = __floats2half2_rn(v2, v3);
                ps0 += v0 + v1; ps1 += v2 + v3;
                pq0 += v0 * v0 + v1 * v1; pq1 += v2 * v2 + v3 * v3;
            }
            atomicAdd(&s_sum[r0], ps0);
            atomicAdd(&s_sq[r0], pq0);
            atomicAdd(&s_sum[r0 + 8], ps1);
            atomicAdd(&s_sq[r0 + 8], pq1);
        }
    }
    __syncthreads();
    if (tid < BM) {
        g_psum[ny][(b0 + tid) * K_SZ + k] = s_sum[tid];
        g_psq[ny][(b0 + tid) * K_SZ + k] = s_sq[tid];
    }
}

// ---------------------------------------------------------------------------
// Combine: theta_e = ln_g*(sum_k a_k*v - c) + ln_b + th0 ; then x_prime.
// Vectorized: 256 threads x 2 elements (half2 path).
// ---------------------------------------------------------------------------
__global__ void __launch_bounds__(256) combine_kernel(
    const float* __restrict__ x_l, const float* __restrict__ ln_g,
    const float* __restrict__ ln_b, const float* __restrict__ theta0,
    float* __restrict__ out) {
    __shared__ float s_a[K_SZ], s_am[K_SZ];
    __shared__ float th[D_SZ];
    const int b = blockIdx.x;
    const int tid = threadIdx.x;

    if (tid < K_SZ) {
        int idx = b * K_SZ + tid;
        float su = g_psum[0][idx] + g_psum[1][idx];
        float sq = g_psq[0][idx] + g_psq[1][idx];
        float mu = su * (1.0f / (float)D_SZ);
        float var = sq * (1.0f / (float)D_SZ) - mu * mu;
        float rs = rsqrtf(var + LN_EPS);
        float a = g_gates[idx] * rs;
        s_a[tid] = a;
        s_am[tid] = a * mu;
    }
    __syncthreads();

    float cc = 0.0f;
#pragma unroll
    for (int kk = 0; kk < K_SZ; kk++) cc += s_am[kk];

    const __half2* rawb = (const __half2*)&g_raw[(size_t)b * K_SZ * D_SZ];
    {
        float ax = 0.0f, ay = 0.0f;
#pragma unroll
        for (int kk = 0; kk < K_SZ; kk++) {
            float2 f = __half22float2(rawb[kk * (D_SZ / 2) + tid]);
            ax = fmaf(s_a[kk], f.x, ax);
            ay = fmaf(s_a[kk], f.y, ay);
        }
        float2 lg = *(const float2*)&ln_g[2 * tid];
        float2 lb = *(const float2*)&ln_b[2 * tid];
        float2 t0 = *(const float2*)&theta0[2 * tid];
        float tx = fmaf(lg.x, ax - cc, lb.x) + t0.x;
        float ty = fmaf(lg.y, ay - cc, lb.y) + t0.y;
        th[2 * tid] = tx;
        th[2 * tid + 1] = ty;
        *(float2*)&out[(size_t)B_SZ * XP_DIM + (size_t)b * D_SZ + 2 * tid] =
            make_float2(tx, ty);
    }
    __syncthreads();

    if (tid < XP_DIM) {
        float xp = 0.0f;
#pragma unroll
        for (int i = 0; i < IN_DIM; i++)
            xp = fmaf(x_l[b * IN_DIM + i], th[i * XP_DIM + tid], xp);
        out[b * XP_DIM + tid] = xp;
    }
}

// ---------------------------------------------------------------------------
extern "C" void kernel_launch(void* const* d_in, const int* in_sizes, int n_in,
                              void* d_out, int out_size) {
    const float* h_prev = (const float*)d_in[0];
    const float* x_l    = (const float*)d_in[1];
    const float* x_ext  = (const float*)d_in[2];
    const float* w1     = (const float*)d_in[3];
    const float* b1     = (const float*)d_in[4];
    const float* w2     = (const float*)d_in[5];
    const float* b2     = (const float*)d_in[6];
    const float* gw1    = (const float*)d_in[7];
    const float* gb1    = (const float*)d_in[8];
    const float* gw2    = (const float*)d_in[9];
    const float* gb2    = (const float*)d_in[10];
    const float* ln_g   = (const float*)d_in[11];
    const float* ln_b   = (const float*)d_in[12];
    const float* th0    = (const float*)d_in[13];
    float* out = (float*)d_out;

    cudaFuncSetAttribute(expert_gemm_kernel,
                         cudaFuncAttributeMaxDynamicSharedMemorySize, GEMM_SMEM);

    prep_gating_kernel<<<2048 + B_SZ / 8, 256>>>(w2, h_prev, gw1, gb1, gw2, gb2);
    expert_gemm_kernel<<<dim3(B_SZ / BM, 2, K_SZ), 256, GEMM_SMEM>>>(x_ext, w1, b1, b2);
    combine_kernel<<<B_SZ, 256>>>(x_l, ln_g, ln_b, th0, out);
}

// round 6
// speedup vs baseline: 6.5300x; 1.0980x over previous
#include <cuda_runtime.h>
#include <cuda_fp16.h>
#include <math.h>
#include <stdint.h>

#define B_SZ   4096
#define H_SZ   256
#define K_SZ   16
#define D_SZ   512
#define IN_DIM 8
#define XP_DIM 64
#define LN_EPS 1e-5f

// GEMM tiling: CTA = 128 rows x 256 cols x 1 expert, 8 warps (2m x 4n), 64x64 each
#define BM 128
#define BN 256
#define BK 32
#define SA 40                     // A smem row stride (halves)
#define SB 264                    // B smem row stride (halves)
#define A_BYTES (BM * SA * 2)     // 10240
#define B_BYTES (BK * SB * 2)     // 16896
#define STAGE (A_BYTES + B_BYTES) // 27136
#define NSTAGE 4
#define GEMM_SMEM (NSTAGE * STAGE)  // 108544

// prep grid layout
#define NB_GATE 256
#define NB_W2   2048
#define NB_A    8192
#define NB_PREP (NB_GATE + NB_W2 + NB_A)

// ---------------- scratch -----------------------------------------------
__device__ __half g_raw[(size_t)B_SZ * K_SZ * D_SZ];   // post-tanh h2 (64MB)
__device__ __half g_A[(size_t)K_SZ * B_SZ * D_SZ];     // tanh(x*w1+b1) fp16 (64MB)
__device__ float  g_psum[2][B_SZ * K_SZ];
__device__ float  g_psq[2][B_SZ * K_SZ];
__device__ float  g_gates[B_SZ * K_SZ];
__device__ __half g_Bhi[(size_t)K_SZ * D_SZ * D_SZ];   // 16*w2 fp16, [k][d][e]

// ---------------- helpers ------------------------------------------------
__device__ __forceinline__ float fast_tanh(float x) {
    float e = __expf(2.0f * x);
    return 1.0f - __fdividef(2.0f, e + 1.0f);
}

__device__ __forceinline__ uint32_t smem_u32(const void* p) {
    uint32_t a;
    asm("{ .reg .u64 t; cvta.to.shared.u64 t, %1; cvt.u32.u64 %0, t; }"
        : "=r"(a) : "l"(p));
    return a;
}

__device__ __forceinline__ void cp16(uint32_t dst, const void* src) {
    asm volatile("cp.async.cg.shared.global [%0], [%1], 16;" :: "r"(dst), "l"(src));
}

__device__ __forceinline__ void ldsm4(uint32_t* r, uint32_t a) {
    asm volatile("ldmatrix.sync.aligned.m8n8.x4.shared.b16 {%0,%1,%2,%3}, [%4];"
                 : "=r"(r[0]), "=r"(r[1]), "=r"(r[2]), "=r"(r[3]) : "r"(a));
}

__device__ __forceinline__ void ldsm4t(uint32_t* r, uint32_t a) {
    asm volatile("ldmatrix.sync.aligned.m8n8.x4.trans.shared.b16 {%0,%1,%2,%3}, [%4];"
                 : "=r"(r[0]), "=r"(r[1]), "=r"(r[2]), "=r"(r[3]) : "r"(a));
}

__device__ __forceinline__ void mma16816(float* c, const uint32_t* a,
                                         uint32_t b0, uint32_t b1) {
    asm volatile(
        "mma.sync.aligned.m16n8k16.row.col.f32.f16.f16.f32 "
        "{%0,%1,%2,%3}, {%4,%5,%6,%7}, {%8,%9}, {%0,%1,%2,%3};"
        : "+f"(c[0]), "+f"(c[1]), "+f"(c[2]), "+f"(c[3])
        : "r"(a[0]), "r"(a[1]), "r"(a[2]), "r"(a[3]), "r"(b0), "r"(b1));
}

// ---------------------------------------------------------------------------
// Fused prep: gating (blocks 0..255, 16 rows each) + w2->fp16 (next 2048)
// + A precompute (next 8192).
// ---------------------------------------------------------------------------
__global__ void __launch_bounds__(256) prep_kernel(
    const float* __restrict__ w2, const float* __restrict__ x_ext,
    const float* __restrict__ w1, const float* __restrict__ b1,
    const float* __restrict__ h_prev, const float* __restrict__ gw1,
    const float* __restrict__ gb1, const float* __restrict__ gw2,
    const float* __restrict__ gb2) {
    const int tid = threadIdx.x;
    const int bid = blockIdx.x;

    if (bid >= NB_GATE + NB_W2) {
        // ---- A precompute: 16 halves per thread ----
        int aid = bid - (NB_GATE + NB_W2);
        size_t t16 = ((size_t)aid * 256 + tid) * 16;
        int d0 = (int)(t16 & 511);
        int bk = (int)(t16 >> 9);
        int b = bk & 4095, k = bk >> 12;
        float xv = x_ext[b * K_SZ + k];
        union { __half h[16]; uint4 u[2]; } H;
#pragma unroll
        for (int g = 0; g < 4; g++) {
            float4 wv = *(const float4*)&w1[k * D_SZ + d0 + g * 4];
            float4 bv = *(const float4*)&b1[k * D_SZ + d0 + g * 4];
            H.h[g * 4 + 0] = __float2half_rn(fast_tanh(fmaf(xv, wv.x, bv.x)));
            H.h[g * 4 + 1] = __float2half_rn(fast_tanh(fmaf(xv, wv.y, bv.y)));
            H.h[g * 4 + 2] = __float2half_rn(fast_tanh(fmaf(xv, wv.z, bv.z)));
            H.h[g * 4 + 3] = __float2half_rn(fast_tanh(fmaf(xv, wv.w, bv.w)));
        }
        __half* dst = g_A + ((size_t)k * B_SZ + b) * D_SZ + d0;
        *(uint4*)dst = H.u[0];
        *(uint4*)(dst + 8) = H.u[1];
        return;
    }

    if (bid >= NB_GATE) {
        // ---- w2 -> 16*w2 fp16 ----
        size_t idx = ((size_t)(bid - NB_GATE) * 256 + tid) * 8;
        float4 v0 = *(const float4*)(w2 + idx);
        float4 v1 = *(const float4*)(w2 + idx + 4);
        float v[8] = {v0.x, v0.y, v0.z, v0.w, v1.x, v1.y, v1.z, v1.w};
        union { __half h[8]; uint4 u; } H;
#pragma unroll
        for (int j = 0; j < 8; j++)
            H.h[j] = __float2half_rn(v[j] * 16.0f);
        *(uint4*)(g_Bhi + idx) = H.u;
        return;
    }

    // ---- gating: 16 rows per block ----
    __shared__ float hsT[H_SZ][20];     // [i][r], pad 20 (16B-aligned rows)
    __shared__ float ts[16][H_SZ];      // [r][i]
    __shared__ float gw2s[H_SZ * K_SZ]; // [i][k]
    const int b0 = bid * 16;

    for (int idx = tid; idx < 16 * H_SZ; idx += 256) {
        int r = idx >> 8, i = idx & 255;
        hsT[i][r] = h_prev[(b0 + r) * H_SZ + i];
    }
    for (int idx = tid; idx < H_SZ * K_SZ / 4; idx += 256)
        ((float4*)gw2s)[idx] = ((const float4*)gw2)[idx];
    __syncthreads();

    // layer1: thread = output col j, 16 rows in regs
    {
        const int j = tid;
        float acc[16];
        float bb = gb1[j];
#pragma unroll
        for (int r = 0; r < 16; r++) acc[r] = bb;
#pragma unroll 4
        for (int i = 0; i < H_SZ; i++) {
            float w = gw1[i * H_SZ + j];
            const float4* hp = (const float4*)&hsT[i][0];
            float4 a0 = hp[0], a1 = hp[1], a2 = hp[2], a3 = hp[3];
            acc[0]  = fmaf(a0.x, w, acc[0]);
            acc[1]  = fmaf(a0.y, w, acc[1]);
            acc[2]  = fmaf(a0.z, w, acc[2]);
            acc[3]  = fmaf(a0.w, w, acc[3]);
            acc[4]  = fmaf(a1.x, w, acc[4]);
            acc[5]  = fmaf(a1.y, w, acc[5]);
            acc[6]  = fmaf(a1.z, w, acc[6]);
            acc[7]  = fmaf(a1.w, w, acc[7]);
            acc[8]  = fmaf(a2.x, w, acc[8]);
            acc[9]  = fmaf(a2.y, w, acc[9]);
            acc[10] = fmaf(a2.z, w, acc[10]);
            acc[11] = fmaf(a2.w, w, acc[11]);
            acc[12] = fmaf(a3.x, w, acc[12]);
            acc[13] = fmaf(a3.y, w, acc[13]);
            acc[14] = fmaf(a3.z, w, acc[14]);
            acc[15] = fmaf(a3.w, w, acc[15]);
        }
#pragma unroll
        for (int r = 0; r < 16; r++) ts[r][j] = fast_tanh(acc[r]);
    }
    __syncthreads();

    // layer2 + softmax: thread = (r, kk), r = tid>>4, kk = tid&15
    {
        const int r = tid >> 4, kk = tid & 15;
        float l = gb2[kk];
#pragma unroll 8
        for (int i = 0; i < H_SZ; i += 4) {
            float4 t4 = *(const float4*)&ts[r][i];
            l = fmaf(t4.x, gw2s[(i + 0) * K_SZ + kk], l);
            l = fmaf(t4.y, gw2s[(i + 1) * K_SZ + kk], l);
            l = fmaf(t4.z, gw2s[(i + 2) * K_SZ + kk], l);
            l = fmaf(t4.w, gw2s[(i + 3) * K_SZ + kk], l);
        }
        float m = l;
#pragma unroll
        for (int o = 8; o > 0; o >>= 1)
            m = fmaxf(m, __shfl_xor_sync(0xffffffffu, m, o));
        float e = __expf(l - m);
        float s = e;
#pragma unroll
        for (int o = 8; o > 0; o >>= 1)
            s += __shfl_xor_sync(0xffffffffu, s, o);
        g_gates[(b0 + r) * K_SZ + kk] = e / s;
    }
}

// ---------------------------------------------------------------------------
// Expert GEMM, fp16: acc = sum_d a*b, result = 16*true. Pure cp/ldsm/mma loop.
// Grid (32, 2, 16): (m-block, n-half, expert). 256 threads, 4-stage cp.async.
// ---------------------------------------------------------------------------
__device__ __forceinline__ void cp_B(int c, int k, int n0, uint32_t stage) {
    const int tid = threadIdx.x;
    const __half* src = g_Bhi + ((size_t)(k * D_SZ + c * BK)) * D_SZ + n0;
    uint32_t bs = stage + A_BYTES;
#pragma unroll
    for (int i = 0; i < 4; i++) {
        int idx = tid + i * 256;
        int row = idx >> 5, ch = idx & 31;
        cp16(bs + row * (SB * 2) + ch * 16, src + (size_t)row * D_SZ + ch * 8);
    }
}

__device__ __forceinline__ void cp_A(int c, int k, int b0, uint32_t stage) {
    const int tid = threadIdx.x;
    const __half* src = g_A + ((size_t)k * B_SZ + b0) * D_SZ + c * BK;
#pragma unroll
    for (int i = 0; i < 2; i++) {
        int idx = tid + i * 256;
        int m = idx >> 2, ch = idx & 3;
        cp16(stage + m * (SA * 2) + ch * 16, src + (size_t)m * D_SZ + ch * 8);
    }
}

__global__ void __launch_bounds__(256, 1)
expert_gemm_kernel(const float* __restrict__ b2) {
    extern __shared__ __align__(128) char sm[];
    __shared__ float s_b2[BN];
    __shared__ float s_sum[BM], s_sq[BM];

    const int tid = threadIdx.x, wid = tid >> 5, lane = tid & 31;
    const int b0 = blockIdx.x * BM, ny = blockIdx.y, k = blockIdx.z;
    const int n0 = ny * BN;
    const int wm = (wid >> 2) * 64, wn = (wid & 3) * 64;
    const uint32_t smb = smem_u32(sm);

    if (tid < BM) {
        s_sum[tid] = 0.0f;
        s_sq[tid] = 0.0f;
    }
    if (tid < BN) s_b2[tid] = b2[k * D_SZ + n0 + tid];

    const int row16 = (lane & 7) + ((lane >> 3) & 1) * 8;
    const int seg8  = ((lane >> 4) & 1) * 8;

    float acc[4][8][4];
#pragma unroll
    for (int a = 0; a < 4; a++)
#pragma unroll
        for (int b = 0; b < 8; b++)
#pragma unroll
            for (int q = 0; q < 4; q++) acc[a][b][q] = 0.0f;

    // prologue: stages 0..2
#pragma unroll
    for (int s = 0; s < 3; s++) {
        uint32_t st = smb + (uint32_t)s * STAGE;
        cp_A(s, k, b0, st);
        cp_B(s, k, n0, st);
        asm volatile("cp.async.commit_group;");
    }

    for (int c = 0; c < D_SZ / BK; c++) {
        const uint32_t st = smb + (uint32_t)(c & 3) * STAGE;
        if (c <= 13)
            asm volatile("cp.async.wait_group 2;" ::: "memory");
        else if (c == 14)
            asm volatile("cp.async.wait_group 1;" ::: "memory");
        else
            asm volatile("cp.async.wait_group 0;" ::: "memory");
        __syncthreads();

        if (c + 3 < D_SZ / BK) {
            const uint32_t nst = smb + (uint32_t)((c + 3) & 3) * STAGE;
            cp_A(c + 3, k, b0, nst);
            cp_B(c + 3, k, n0, nst);
            asm volatile("cp.async.commit_group;");
        }

        const uint32_t As = st, Bh = st + A_BYTES;
#pragma unroll
        for (int kk = 0; kk < 2; kk++) {
            uint32_t ah[4][4];
#pragma unroll
            for (int mb = 0; mb < 4; mb++)
                ldsm4(ah[mb], As + (uint32_t)((wm + mb * 16 + row16) * (SA * 2) +
                                              (kk * 16 + seg8) * 2));
#pragma unroll
            for (int p = 0; p < 4; p++) {
                uint32_t bh[4];
                ldsm4t(bh, Bh + (uint32_t)((kk * 16 + row16) * (SB * 2) +
                                           (wn + p * 16 + seg8) * 2));
#pragma unroll
                for (int mb = 0; mb < 4; mb++) {
                    mma16816(acc[mb][2 * p],     ah[mb], bh[0], bh[1]);
                    mma16816(acc[mb][2 * p + 1], ah[mb], bh[2], bh[3]);
                }
            }
        }
    }

    // Epilogue: v = tanh(acc/16 + b2); fp16 store; LN partial stats.
    {
        const int q = lane >> 2, c2 = (lane & 3) * 2;
#pragma unroll
        for (int mb = 0; mb < 4; mb++) {
            const int r0 = wm + mb * 16 + q;
            __half* o0 = &g_raw[((size_t)(b0 + r0) * K_SZ + k) * D_SZ + n0];
            __half* o1 = &g_raw[((size_t)(b0 + r0 + 8) * K_SZ + k) * D_SZ + n0];
            float ps0 = 0.f, ps1 = 0.f, pq0 = 0.f, pq1 = 0.f;
#pragma unroll
            for (int nb = 0; nb < 8; nb++) {
                const int e = wn + nb * 8 + c2;
                float bb0 = s_b2[e], bb1 = s_b2[e + 1];
                float v0 = fast_tanh(fmaf(acc[mb][nb][0], 0.0625f, bb0));
                float v1 = fast_tanh(fmaf(acc[mb][nb][1], 0.0625f, bb1));
                float v2 = fast_tanh(fmaf(acc[mb][nb][2], 0.0625f, bb0));
                float v3 = fast_tanh(fmaf(acc[mb][nb][3], 0.0625f, bb1));
                *(__half2*)(o0 + e) = __floats2half2_rn(v0, v1);
                *(__half2*)(o1 + e) = __floats2half2_rn(v2, v3);
                ps0 += v0 + v1; ps1 += v2 + v3;
                pq0 += v0 * v0 + v1 * v1; pq1 += v2 * v2 + v3 * v3;
            }
            atomicAdd(&s_sum[r0], ps0);
            atomicAdd(&s_sq[r0], pq0);
            atomicAdd(&s_sum[r0 + 8], ps1);
            atomicAdd(&s_sq[r0 + 8], pq1);
        }
    }
    __syncthreads();
    if (tid < BM) {
        g_psum[ny][(b0 + tid) * K_SZ + k] = s_sum[tid];
        g_psq[ny][(b0 + tid) * K_SZ + k] = s_sq[tid];
    }
}

// ---------------------------------------------------------------------------
// Combine: theta_e = ln_g*(sum_k a_k*v - c) + ln_b + th0 ; then x_prime.
// ---------------------------------------------------------------------------
__global__ void __launch_bounds__(256) combine_kernel(
    const float* __restrict__ x_l, const float* __restrict__ ln_g,
    const float* __restrict__ ln_b, const float* __restrict__ theta0,
    float* __restrict__ out) {
    __shared__ float s_a[K_SZ], s_am[K_SZ];
    __shared__ float th[D_SZ];
    const int b = blockIdx.x;
    const int tid = threadIdx.x;

    if (tid < K_SZ) {
        int idx = b * K_SZ + tid;
        float su = g_psum[0][idx] + g_psum[1][idx];
        float sq = g_psq[0][idx] + g_psq[1][idx];
        float mu = su * (1.0f / (float)D_SZ);
        float var = sq * (1.0f / (float)D_SZ) - mu * mu;
        float rs = rsqrtf(var + LN_EPS);
        float a = g_gates[idx] * rs;
        s_a[tid] = a;
        s_am[tid] = a * mu;
    }
    __syncthreads();

    float cc = 0.0f;
#pragma unroll
    for (int kk = 0; kk < K_SZ; kk++) cc += s_am[kk];

    const __half2* rawb = (const __half2*)&g_raw[(size_t)b * K_SZ * D_SZ];
    {
        float ax = 0.0f, ay = 0.0f;
#pragma unroll
        for (int kk = 0; kk < K_SZ; kk++) {
            float2 f = __half22float2(rawb[kk * (D_SZ / 2) + tid]);
            ax = fmaf(s_a[kk], f.x, ax);
            ay = fmaf(s_a[kk], f.y, ay);
        }
        float2 lg = *(const float2*)&ln_g[2 * tid];
        float2 lb = *(const float2*)&ln_b[2 * tid];
        float2 t0 = *(const float2*)&theta0[2 * tid];
        float tx = fmaf(lg.x, ax - cc, lb.x) + t0.x;
        float ty = fmaf(lg.y, ay - cc, lb.y) + t0.y;
        th[2 * tid] = tx;
        th[2 * tid + 1] = ty;
        *(float2*)&out[(size_t)B_SZ * XP_DIM + (size_t)b * D_SZ + 2 * tid] =
            make_float2(tx, ty);
    }
    __syncthreads();

    if (tid < XP_DIM) {
        float xp = 0.0f;
#pragma unroll
        for (int i = 0; i < IN_DIM; i++)
            xp = fmaf(x_l[b * IN_DIM + i], th[i * XP_DIM + tid], xp);
        out[b * XP_DIM + tid] = xp;
    }
}

// ---------------------------------------------------------------------------
extern "C" void kernel_launch(void* const* d_in, const int* in_sizes, int n_in,
                              void* d_out, int out_size) {
    const float* h_prev = (const float*)d_in[0];
    const float* x_l    = (const float*)d_in[1];
    const float* x_ext  = (const float*)d_in[2];
    const float* w1     = (const float*)d_in[3];
    const float* b1     = (const float*)d_in[4];
    const float* w2     = (const float*)d_in[5];
    const float* b2     = (const float*)d_in[6];
    const float* gw1    = (const float*)d_in[7];
    const float* gb1    = (const float*)d_in[8];
    const float* gw2    = (const float*)d_in[9];
    const float* gb2    = (const float*)d_in[10];
    const float* ln_g   = (const float*)d_in[11];
    const float* ln_b   = (const float*)d_in[12];
    const float* th0    = (const float*)d_in[13];
    float* out = (float*)d_out;

    cudaFuncSetAttribute(expert_gemm_kernel,
                         cudaFuncAttributeMaxDynamicSharedMemorySize, GEMM_SMEM);

    prep_kernel<<<NB_PREP, 256>>>(w2, x_ext, w1, b1, h_prev, gw1, gb1, gw2, gb2);
    expert_gemm_kernel<<<dim3(B_SZ / BM, 2, K_SZ), 256, GEMM_SMEM>>>(b2);
    combine_kernel<<<B_SZ, 256>>>(x_l, ln_g, ln_b, th0, out);
}

// round 7
// speedup vs baseline: 7.7078x; 1.1804x over previous
#include <cuda_runtime.h>
#include <cuda_fp16.h>
#include <math.h>
#include <stdint.h>

#define B_SZ   4096
#define H_SZ   256
#define K_SZ   16
#define D_SZ   512
#define IN_DIM 8
#define XP_DIM 64
#define LN_EPS 1e-5f

// GEMM tiling: CTA = 128 rows x 256 cols x 1 expert, 8 warps (2m x 4n), 64x64 each
#define BM 128
#define BN 256
#define BK 64
#define SA 72                     // A smem row stride (halves)
#define SB 264                    // B smem row stride (halves)
#define A_BYTES (BM * SA * 2)     // 18432
#define B_BYTES (BK * SB * 2)     // 33792
#define STAGE (A_BYTES + B_BYTES) // 52224
#define NSTAGE 3
#define GEMM_SMEM (NSTAGE * STAGE)  // 156672
#define NITER (D_SZ / BK)           // 8

// prep grid layout
#define NB_GATE 256
#define NB_W2   2048
#define NB_AGEN 512
#define NB_PREP (NB_GATE + NB_W2 + NB_AGEN)

// combine smem row stride (floats): pad 16 for conflict-free strided reduce
#define SVR (D_SZ + 16)

// ---------------- scratch -----------------------------------------------
__device__ __half g_raw[(size_t)B_SZ * K_SZ * D_SZ];   // pre-tanh h2 (64MB)
__device__ __half g_A[(size_t)K_SZ * B_SZ * D_SZ];     // tanh(x*w1+b1) fp16 (64MB)
__device__ float  g_gates[B_SZ * K_SZ];
__device__ __half g_Bhi[(size_t)K_SZ * D_SZ * D_SZ];   // 16*w2 fp16, [k][d][e]

// ---------------- helpers ------------------------------------------------
__device__ __forceinline__ float fast_tanh(float x) {
    float e = __expf(2.0f * x);
    return 1.0f - __fdividef(2.0f, e + 1.0f);
}

__device__ __forceinline__ uint32_t smem_u32(const void* p) {
    uint32_t a;
    asm("{ .reg .u64 t; cvta.to.shared.u64 t, %1; cvt.u32.u64 %0, t; }"
        : "=r"(a) : "l"(p));
    return a;
}

__device__ __forceinline__ void cp16(uint32_t dst, const void* src) {
    asm volatile("cp.async.cg.shared.global [%0], [%1], 16;" :: "r"(dst), "l"(src));
}

__device__ __forceinline__ void ldsm4(uint32_t* r, uint32_t a) {
    asm volatile("ldmatrix.sync.aligned.m8n8.x4.shared.b16 {%0,%1,%2,%3}, [%4];"
                 : "=r"(r[0]), "=r"(r[1]), "=r"(r[2]), "=r"(r[3]) : "r"(a));
}

__device__ __forceinline__ void ldsm4t(uint32_t* r, uint32_t a) {
    asm volatile("ldmatrix.sync.aligned.m8n8.x4.trans.shared.b16 {%0,%1,%2,%3}, [%4];"
                 : "=r"(r[0]), "=r"(r[1]), "=r"(r[2]), "=r"(r[3]) : "r"(a));
}

__device__ __forceinline__ void mma16816(float* c, const uint32_t* a,
                                         uint32_t b0, uint32_t b1) {
    asm volatile(
        "mma.sync.aligned.m16n8k16.row.col.f32.f16.f16.f32 "
        "{%0,%1,%2,%3}, {%4,%5,%6,%7}, {%8,%9}, {%0,%1,%2,%3};"
        : "+f"(c[0]), "+f"(c[1]), "+f"(c[2]), "+f"(c[3])
        : "r"(a[0]), "r"(a[1]), "r"(a[2]), "r"(a[3]), "r"(b0), "r"(b1));
}

// ---------------------------------------------------------------------------
// Fused prep: gating (0..255) + w2->fp16 (256..2303) + A precompute (2304..2815)
// ---------------------------------------------------------------------------
__global__ void __launch_bounds__(256) prep_kernel(
    const float* __restrict__ w2, const float* __restrict__ x_ext,
    const float* __restrict__ w1, const float* __restrict__ b1,
    const float* __restrict__ h_prev, const float* __restrict__ gw1,
    const float* __restrict__ gb1, const float* __restrict__ gw2,
    const float* __restrict__ gb2) {
    const int tid = threadIdx.x;
    const int bid = blockIdx.x;

    if (bid >= NB_GATE + NB_W2) {
        // ---- A precompute: thread owns fixed d-chunk (regs), loops 32 b-rows
        __shared__ float sx[128];
        const int aid = bid - (NB_GATE + NB_W2);
        const int k = aid >> 5;
        const int b0 = (aid & 31) * 128;
        const int g = tid & 63, q = tid >> 6;

        if (tid < 128) sx[tid] = x_ext[(b0 + tid) * K_SZ + k];
        const float4 wa = *(const float4*)&w1[k * D_SZ + g * 8];
        const float4 wb = *(const float4*)&w1[k * D_SZ + g * 8 + 4];
        const float4 ba = *(const float4*)&b1[k * D_SZ + g * 8];
        const float4 bb = *(const float4*)&b1[k * D_SZ + g * 8 + 4];
        __syncthreads();

#pragma unroll 4
        for (int it = 0; it < 32; it++) {
            int m = q * 32 + it;
            float xv = sx[m];
            union { __half h[8]; uint4 u; } H;
            H.h[0] = __float2half_rn(fast_tanh(fmaf(xv, wa.x, ba.x)));
            H.h[1] = __float2half_rn(fast_tanh(fmaf(xv, wa.y, ba.y)));
            H.h[2] = __float2half_rn(fast_tanh(fmaf(xv, wa.z, ba.z)));
            H.h[3] = __float2half_rn(fast_tanh(fmaf(xv, wa.w, ba.w)));
            H.h[4] = __float2half_rn(fast_tanh(fmaf(xv, wb.x, bb.x)));
            H.h[5] = __float2half_rn(fast_tanh(fmaf(xv, wb.y, bb.y)));
            H.h[6] = __float2half_rn(fast_tanh(fmaf(xv, wb.z, bb.z)));
            H.h[7] = __float2half_rn(fast_tanh(fmaf(xv, wb.w, bb.w)));
            *(uint4*)(g_A + ((size_t)k * B_SZ + b0 + m) * D_SZ + g * 8) = H.u;
        }
        return;
    }

    if (bid >= NB_GATE) {
        // ---- w2 -> 16*w2 fp16 ----
        size_t idx = ((size_t)(bid - NB_GATE) * 256 + tid) * 8;
        float4 v0 = *(const float4*)(w2 + idx);
        float4 v1 = *(const float4*)(w2 + idx + 4);
        float v[8] = {v0.x, v0.y, v0.z, v0.w, v1.x, v1.y, v1.z, v1.w};
        union { __half h[8]; uint4 u; } H;
#pragma unroll
        for (int j = 0; j < 8; j++)
            H.h[j] = __float2half_rn(v[j] * 16.0f);
        *(uint4*)(g_Bhi + idx) = H.u;
        return;
    }

    // ---- gating: 16 rows per block ----
    __shared__ float hsT[H_SZ][20];
    __shared__ float ts[16][H_SZ];
    __shared__ float gw2s[H_SZ * K_SZ];
    const int b0 = bid * 16;

    for (int idx = tid; idx < 16 * H_SZ; idx += 256) {
        int r = idx >> 8, i = idx & 255;
        hsT[i][r] = h_prev[(b0 + r) * H_SZ + i];
    }
    for (int idx = tid; idx < H_SZ * K_SZ / 4; idx += 256)
        ((float4*)gw2s)[idx] = ((const float4*)gw2)[idx];
    __syncthreads();

    {
        const int j = tid;
        float acc[16];
        float bb = gb1[j];
#pragma unroll
        for (int r = 0; r < 16; r++) acc[r] = bb;
#pragma unroll 4
        for (int i = 0; i < H_SZ; i++) {
            float w = gw1[i * H_SZ + j];
            const float4* hp = (const float4*)&hsT[i][0];
            float4 a0 = hp[0], a1 = hp[1], a2 = hp[2], a3 = hp[3];
            acc[0]  = fmaf(a0.x, w, acc[0]);
            acc[1]  = fmaf(a0.y, w, acc[1]);
            acc[2]  = fmaf(a0.z, w, acc[2]);
            acc[3]  = fmaf(a0.w, w, acc[3]);
            acc[4]  = fmaf(a1.x, w, acc[4]);
            acc[5]  = fmaf(a1.y, w, acc[5]);
            acc[6]  = fmaf(a1.z, w, acc[6]);
            acc[7]  = fmaf(a1.w, w, acc[7]);
            acc[8]  = fmaf(a2.x, w, acc[8]);
            acc[9]  = fmaf(a2.y, w, acc[9]);
            acc[10] = fmaf(a2.z, w, acc[10]);
            acc[11] = fmaf(a2.w, w, acc[11]);
            acc[12] = fmaf(a3.x, w, acc[12]);
            acc[13] = fmaf(a3.y, w, acc[13]);
            acc[14] = fmaf(a3.z, w, acc[14]);
            acc[15] = fmaf(a3.w, w, acc[15]);
        }
#pragma unroll
        for (int r = 0; r < 16; r++) ts[r][j] = fast_tanh(acc[r]);
    }
    __syncthreads();

    {
        const int r = tid >> 4, kk = tid & 15;
        float l = gb2[kk];
#pragma unroll 8
        for (int i = 0; i < H_SZ; i += 4) {
            float4 t4 = *(const float4*)&ts[r][i];
            l = fmaf(t4.x, gw2s[(i + 0) * K_SZ + kk], l);
            l = fmaf(t4.y, gw2s[(i + 1) * K_SZ + kk], l);
            l = fmaf(t4.z, gw2s[(i + 2) * K_SZ + kk], l);
            l = fmaf(t4.w, gw2s[(i + 3) * K_SZ + kk], l);
        }
        float m = l;
#pragma unroll
        for (int o = 8; o > 0; o >>= 1)
            m = fmaxf(m, __shfl_xor_sync(0xffffffffu, m, o));
        float e = __expf(l - m);
        float s = e;
#pragma unroll
        for (int o = 8; o > 0; o >>= 1)
            s += __shfl_xor_sync(0xffffffffu, s, o);
        g_gates[(b0 + r) * K_SZ + kk] = e / s;
    }
}

// ---------------------------------------------------------------------------
// Expert GEMM, fp16: acc = sum_d a*b (=16*true). BK=64, 3 stages, 8 iters.
// Epilogue stores PRE-tanh (acc/16 + b2) as fp16 — tanh/LN moved to combine.
// ---------------------------------------------------------------------------
__device__ __forceinline__ void cp_B(int c, int k, int n0, uint32_t stage) {
    const int tid = threadIdx.x;
    const __half* src = g_Bhi + ((size_t)(k * D_SZ + c * BK)) * D_SZ + n0;
    uint32_t bs = stage + A_BYTES;
#pragma unroll
    for (int i = 0; i < 8; i++) {
        int idx = tid + i * 256;
        int row = idx >> 5, ch = idx & 31;
        cp16(bs + row * (SB * 2) + ch * 16, src + (size_t)row * D_SZ + ch * 8);
    }
}

__device__ __forceinline__ void cp_A(int c, int k, int b0, uint32_t stage) {
    const int tid = threadIdx.x;
    const __half* src = g_A + ((size_t)k * B_SZ + b0) * D_SZ + c * BK;
#pragma unroll
    for (int i = 0; i < 4; i++) {
        int idx = tid + i * 256;
        int m = idx >> 3, ch = idx & 7;
        cp16(stage + m * (SA * 2) + ch * 16, src + (size_t)m * D_SZ + ch * 8);
    }
}

__global__ void __launch_bounds__(256, 1)
expert_gemm_kernel(const float* __restrict__ b2) {
    extern __shared__ __align__(128) char sm[];
    __shared__ float s_b2[BN];

    const int tid = threadIdx.x, wid = tid >> 5, lane = tid & 31;
    const int b0 = blockIdx.x * BM, ny = blockIdx.y, k = blockIdx.z;
    const int n0 = ny * BN;
    const int wm = (wid >> 2) * 64, wn = (wid & 3) * 64;
    const uint32_t smb = smem_u32(sm);

    if (tid < BN) s_b2[tid] = b2[k * D_SZ + n0 + tid];

    const int row16 = (lane & 7) + ((lane >> 3) & 1) * 8;
    const int seg8  = ((lane >> 4) & 1) * 8;

    float acc[4][8][4];
#pragma unroll
    for (int a = 0; a < 4; a++)
#pragma unroll
        for (int b = 0; b < 8; b++)
#pragma unroll
            for (int q = 0; q < 4; q++) acc[a][b][q] = 0.0f;

    // prologue: stages 0,1
#pragma unroll
    for (int s = 0; s < 2; s++) {
        uint32_t st = smb + (uint32_t)s * STAGE;
        cp_A(s, k, b0, st);
        cp_B(s, k, n0, st);
        asm volatile("cp.async.commit_group;");
    }

    for (int c = 0; c < NITER; c++) {
        const uint32_t st = smb + (uint32_t)(c % NSTAGE) * STAGE;
        if (c < NITER - 1)
            asm volatile("cp.async.wait_group 1;" ::: "memory");
        else
            asm volatile("cp.async.wait_group 0;" ::: "memory");
        __syncthreads();

        if (c + 2 < NITER) {
            const uint32_t nst = smb + (uint32_t)((c + 2) % NSTAGE) * STAGE;
            cp_A(c + 2, k, b0, nst);
            cp_B(c + 2, k, n0, nst);
            asm volatile("cp.async.commit_group;");
        }

        const uint32_t As = st, Bh = st + A_BYTES;
#pragma unroll
        for (int kk = 0; kk < 4; kk++) {
            uint32_t ah[4][4];
#pragma unroll
            for (int mb = 0; mb < 4; mb++)
                ldsm4(ah[mb], As + (uint32_t)((wm + mb * 16 + row16) * (SA * 2) +
                                              (kk * 16 + seg8) * 2));
#pragma unroll
            for (int p = 0; p < 4; p++) {
                uint32_t bh[4];
                ldsm4t(bh, Bh + (uint32_t)((kk * 16 + row16) * (SB * 2) +
                                           (wn + p * 16 + seg8) * 2));
#pragma unroll
                for (int mb = 0; mb < 4; mb++) {
                    mma16816(acc[mb][2 * p],     ah[mb], bh[0], bh[1]);
                    mma16816(acc[mb][2 * p + 1], ah[mb], bh[2], bh[3]);
                }
            }
        }
    }

    // Epilogue: store pre-tanh (acc/16 + b2) fp16. No stats here.
    {
        const int q = lane >> 2, c2 = (lane & 3) * 2;
#pragma unroll
        for (int mb = 0; mb < 4; mb++) {
            const int r0 = wm + mb * 16 + q;
            __half* o0 = &g_raw[((size_t)(b0 + r0) * K_SZ + k) * D_SZ + n0];
            __half* o1 = &g_raw[((size_t)(b0 + r0 + 8) * K_SZ + k) * D_SZ + n0];
#pragma unroll
            for (int nb = 0; nb < 8; nb++) {
                const int e = wn + nb * 8 + c2;
                float bb0 = s_b2[e], bb1 = s_b2[e + 1];
                float v0 = fmaf(acc[mb][nb][0], 0.0625f, bb0);
                float v1 = fmaf(acc[mb][nb][1], 0.0625f, bb1);
                float v2 = fmaf(acc[mb][nb][2], 0.0625f, bb0);
                float v3 = fmaf(acc[mb][nb][3], 0.0625f, bb1);
                *(__half2*)(o0 + e) = __floats2half2_rn(v0, v1);
                *(__half2*)(o1 + e) = __floats2half2_rn(v2, v3);
            }
        }
    }
}

// ---------------------------------------------------------------------------
// Combine: tanh -> smem, per-k LN stats in-block, weighted sum -> theta, x'.
// ---------------------------------------------------------------------------
__global__ void __launch_bounds__(256) combine_kernel(
    const float* __restrict__ x_l, const float* __restrict__ ln_g,
    const float* __restrict__ ln_b, const float* __restrict__ theta0,
    float* __restrict__ out) {
    __shared__ float sv[K_SZ][SVR];     // ~33KB, pad 16 for strided reduce
    __shared__ float th[D_SZ];
    __shared__ float s_sum[K_SZ], s_sq[K_SZ], s_a[K_SZ], s_am[K_SZ];
    const int b = blockIdx.x;
    const int tid = threadIdx.x;

    const __half2* rawb = (const __half2*)&g_raw[(size_t)b * K_SZ * D_SZ];
#pragma unroll
    for (int kk = 0; kk < K_SZ; kk++) {
        float2 f = __half22float2(rawb[kk * (D_SZ / 2) + tid]);
        sv[kk][2 * tid]     = fast_tanh(f.x);
        sv[kk][2 * tid + 1] = fast_tanh(f.y);
    }
    __syncthreads();

    // stats: 16 threads per k, strided reads (conflict-free via pad 16)
    {
        const int k = tid >> 4, sub = tid & 15;
        float s = 0.0f, q = 0.0f;
#pragma unroll
        for (int j = 0; j < 32; j++) {
            float v = sv[k][sub + j * 16];
            s += v;
            q = fmaf(v, v, q);
        }
#pragma unroll
        for (int o = 8; o > 0; o >>= 1) {
            s += __shfl_xor_sync(0xffffffffu, s, o);
            q += __shfl_xor_sync(0xffffffffu, q, o);
        }
        if (sub == 0) {
            s_sum[k] = s;
            s_sq[k] = q;
        }
    }
    __syncthreads();

    if (tid < K_SZ) {
        float mu = s_sum[tid] * (1.0f / (float)D_SZ);
        float var = s_sq[tid] * (1.0f / (float)D_SZ) - mu * mu;
        float rs = rsqrtf(var + LN_EPS);
        float a = g_gates[b * K_SZ + tid] * rs;
        s_a[tid] = a;
        s_am[tid] = a * mu;
    }
    __syncthreads();

    float cc = 0.0f;
#pragma unroll
    for (int kk = 0; kk < K_SZ; kk++) cc += s_am[kk];

    {
        float ax = 0.0f, ay = 0.0f;
#pragma unroll
        for (int kk = 0; kk < K_SZ; kk++) {
            float2 f = *(const float2*)&sv[kk][2 * tid];
            ax = fmaf(s_a[kk], f.x, ax);
            ay = fmaf(s_a[kk], f.y, ay);
        }
        float2 lg = *(const float2*)&ln_g[2 * tid];
        float2 lb = *(const float2*)&ln_b[2 * tid];
        float2 t0 = *(const float2*)&theta0[2 * tid];
        float tx = fmaf(lg.x, ax - cc, lb.x) + t0.x;
        float ty = fmaf(lg.y, ay - cc, lb.y) + t0.y;
        th[2 * tid] = tx;
        th[2 * tid + 1] = ty;
        *(float2*)&out[(size_t)B_SZ * XP_DIM + (size_t)b * D_SZ + 2 * tid] =
            make_float2(tx, ty);
    }
    __syncthreads();

    if (tid < XP_DIM) {
        float xp = 0.0f;
#pragma unroll
        for (int i = 0; i < IN_DIM; i++)
            xp = fmaf(x_l[b * IN_DIM + i], th[i * XP_DIM + tid], xp);
        out[b * XP_DIM + tid] = xp;
    }
}

// ---------------------------------------------------------------------------
extern "C" void kernel_launch(void* const* d_in, const int* in_sizes, int n_in,
                              void* d_out, int out_size) {
    const float* h_prev = (const float*)d_in[0];
    const float* x_l    = (const float*)d_in[1];
    const float* x_ext  = (const float*)d_in[2];
    const float* w1     = (const float*)d_in[3];
    const float* b1     = (const float*)d_in[4];
    const float* w2     = (const float*)d_in[5];
    const float* b2     = (const float*)d_in[6];
    const float* gw1    = (const float*)d_in[7];
    const float* gb1    = (const float*)d_in[8];
    const float* gw2    = (const float*)d_in[9];
    const float* gb2    = (const float*)d_in[10];
    const float* ln_g   = (const float*)d_in[11];
    const float* ln_b   = (const float*)d_in[12];
    const float* th0    = (const float*)d_in[13];
    float* out = (float*)d_out;

    cudaFuncSetAttribute(expert_gemm_kernel,
                         cudaFuncAttributeMaxDynamicSharedMemorySize, GEMM_SMEM);

    prep_kernel<<<NB_PREP, 256>>>(w2, x_ext, w1, b1, h_prev, gw1, gb1, gw2, gb2);
    expert_gemm_kernel<<<dim3(B_SZ / BM, 2, K_SZ), 256, GEMM_SMEM>>>(b2);
    combine_kernel<<<B_SZ, 256>>>(x_l, ln_g, ln_b, th0, out);
}

// round 8
// speedup vs baseline: 8.3364x; 1.0816x over previous
#include <cuda_runtime.h>
#include <cuda_fp16.h>
#include <math.h>
#include <stdint.h>

#define B_SZ   4096
#define H_SZ   256
#define K_SZ   16
#define D_SZ   512
#define IN_DIM 8
#define XP_DIM 64
#define LN_EPS 1e-5f

// GEMM tiling: CTA = 128 x 128 x 1 expert, 8 warps (2m x 4n), 64x32 each
#define BM 128
#define BN 128
#define BK 64
#define SA 72                     // A smem row stride (halves)
#define SB 136                    // B smem row stride (halves)
#define A_BYTES (BM * SA * 2)     // 18432
#define B_BYTES (BK * SB * 2)     // 17408
#define STAGE (A_BYTES + B_BYTES) // 35840
#define NSTAGE 3
#define GEMM_SMEM (NSTAGE * STAGE)  // 107520  (2 CTAs/SM)
#define NITER (D_SZ / BK)           // 8

// prep grid layout
#define NB_GATE 256
#define NB_W2   2048
#define NB_AGEN 1024
#define NB_PREP (NB_GATE + NB_W2 + NB_AGEN)

// combine smem row stride
#define SVR (D_SZ + 16)

// ---------------- scratch -----------------------------------------------
__device__ __half g_raw[(size_t)B_SZ * K_SZ * D_SZ];   // pre-tanh h2 (64MB)
__device__ __half g_A[(size_t)K_SZ * B_SZ * D_SZ];     // tanh(x*w1+b1) fp16 (64MB)
__device__ float  g_gates[B_SZ * K_SZ];
__device__ __half g_Bhi[(size_t)K_SZ * D_SZ * D_SZ];   // 16*w2 fp16, [k][d][e]

// ---------------- helpers ------------------------------------------------
__device__ __forceinline__ float fast_tanh(float x) {     // ~1e-6 err, 2 MUFU
    float e = __expf(2.0f * x);
    return 1.0f - __fdividef(2.0f, e + 1.0f);
}

__device__ __forceinline__ float tanh_approx(float x) {   // 1 MUFU, ~5e-4 abs
    float y;
    asm("tanh.approx.f32 %0, %1;" : "=f"(y) : "f"(x));
    return y;
}

__device__ __forceinline__ uint32_t smem_u32(const void* p) {
    uint32_t a;
    asm("{ .reg .u64 t; cvta.to.shared.u64 t, %1; cvt.u32.u64 %0, t; }"
        : "=r"(a) : "l"(p));
    return a;
}

__device__ __forceinline__ void cp16(uint32_t dst, const void* src) {
    asm volatile("cp.async.cg.shared.global [%0], [%1], 16;" :: "r"(dst), "l"(src));
}

__device__ __forceinline__ void ldsm4(uint32_t* r, uint32_t a) {
    asm volatile("ldmatrix.sync.aligned.m8n8.x4.shared.b16 {%0,%1,%2,%3}, [%4];"
                 : "=r"(r[0]), "=r"(r[1]), "=r"(r[2]), "=r"(r[3]) : "r"(a));
}

__device__ __forceinline__ void ldsm4t(uint32_t* r, uint32_t a) {
    asm volatile("ldmatrix.sync.aligned.m8n8.x4.trans.shared.b16 {%0,%1,%2,%3}, [%4];"
                 : "=r"(r[0]), "=r"(r[1]), "=r"(r[2]), "=r"(r[3]) : "r"(a));
}

__device__ __forceinline__ void mma16816(float* c, const uint32_t* a,
                                         uint32_t b0, uint32_t b1) {
    asm volatile(
        "mma.sync.aligned.m16n8k16.row.col.f32.f16.f16.f32 "
        "{%0,%1,%2,%3}, {%4,%5,%6,%7}, {%8,%9}, {%0,%1,%2,%3};"
        : "+f"(c[0]), "+f"(c[1]), "+f"(c[2]), "+f"(c[3])
        : "r"(a[0]), "r"(a[1]), "r"(a[2]), "r"(a[3]), "r"(b0), "r"(b1));
}

// ---------------------------------------------------------------------------
// Fused prep: gating (0..255) + w2->fp16 (256..2303) + A precompute (2304..)
// ---------------------------------------------------------------------------
__global__ void __launch_bounds__(256) prep_kernel(
    const float* __restrict__ w2, const float* __restrict__ x_ext,
    const float* __restrict__ w1, const float* __restrict__ b1,
    const float* __restrict__ h_prev, const float* __restrict__ gw1,
    const float* __restrict__ gb1, const float* __restrict__ gw2,
    const float* __restrict__ gb2) {
    const int tid = threadIdx.x;
    const int bid = blockIdx.x;

    if (bid >= NB_GATE + NB_W2) {
        // ---- A precompute: 64 rows per block; thread owns d-chunk of 8
        __shared__ float sx[64];
        const int aid = bid - (NB_GATE + NB_W2);
        const int k = aid >> 6;
        const int b0 = (aid & 63) * 64;
        const int g = tid & 63, q = tid >> 6;

        if (tid < 64) sx[tid] = x_ext[(b0 + tid) * K_SZ + k];
        const float4 wa = *(const float4*)&w1[k * D_SZ + g * 8];
        const float4 wb = *(const float4*)&w1[k * D_SZ + g * 8 + 4];
        const float4 ba = *(const float4*)&b1[k * D_SZ + g * 8];
        const float4 bb = *(const float4*)&b1[k * D_SZ + g * 8 + 4];
        __syncthreads();

#pragma unroll 4
        for (int it = 0; it < 16; it++) {
            int m = q * 16 + it;
            float xv = sx[m];
            union { __half h[8]; uint4 u; } H;
            H.h[0] = __float2half_rn(tanh_approx(fmaf(xv, wa.x, ba.x)));
            H.h[1] = __float2half_rn(tanh_approx(fmaf(xv, wa.y, ba.y)));
            H.h[2] = __float2half_rn(tanh_approx(fmaf(xv, wa.z, ba.z)));
            H.h[3] = __float2half_rn(tanh_approx(fmaf(xv, wa.w, ba.w)));
            H.h[4] = __float2half_rn(tanh_approx(fmaf(xv, wb.x, bb.x)));
            H.h[5] = __float2half_rn(tanh_approx(fmaf(xv, wb.y, bb.y)));
            H.h[6] = __float2half_rn(tanh_approx(fmaf(xv, wb.z, bb.z)));
            H.h[7] = __float2half_rn(tanh_approx(fmaf(xv, wb.w, bb.w)));
            *(uint4*)(g_A + ((size_t)k * B_SZ + b0 + m) * D_SZ + g * 8) = H.u;
        }
        return;
    }

    if (bid >= NB_GATE) {
        // ---- w2 -> 16*w2 fp16 ----
        size_t idx = ((size_t)(bid - NB_GATE) * 256 + tid) * 8;
        float4 v0 = *(const float4*)(w2 + idx);
        float4 v1 = *(const float4*)(w2 + idx + 4);
        float v[8] = {v0.x, v0.y, v0.z, v0.w, v1.x, v1.y, v1.z, v1.w};
        union { __half h[8]; uint4 u; } H;
#pragma unroll
        for (int j = 0; j < 8; j++)
            H.h[j] = __float2half_rn(v[j] * 16.0f);
        *(uint4*)(g_Bhi + idx) = H.u;
        return;
    }

    // ---- gating: 16 rows per block ----
    __shared__ float hsT[H_SZ][20];
    __shared__ float ts[16][H_SZ];
    __shared__ float gw2s[H_SZ * K_SZ];
    const int b0 = bid * 16;

    for (int idx = tid; idx < 16 * H_SZ; idx += 256) {
        int r = idx >> 8, i = idx & 255;
        hsT[i][r] = h_prev[(b0 + r) * H_SZ + i];
    }
    for (int idx = tid; idx < H_SZ * K_SZ / 4; idx += 256)
        ((float4*)gw2s)[idx] = ((const float4*)gw2)[idx];
    __syncthreads();

    {
        const int j = tid;
        float acc[16];
        float bb = gb1[j];
#pragma unroll
        for (int r = 0; r < 16; r++) acc[r] = bb;
#pragma unroll 4
        for (int i = 0; i < H_SZ; i++) {
            float w = gw1[i * H_SZ + j];
            const float4* hp = (const float4*)&hsT[i][0];
            float4 a0 = hp[0], a1 = hp[1], a2 = hp[2], a3 = hp[3];
            acc[0]  = fmaf(a0.x, w, acc[0]);
            acc[1]  = fmaf(a0.y, w, acc[1]);
            acc[2]  = fmaf(a0.z, w, acc[2]);
            acc[3]  = fmaf(a0.w, w, acc[3]);
            acc[4]  = fmaf(a1.x, w, acc[4]);
            acc[5]  = fmaf(a1.y, w, acc[5]);
            acc[6]  = fmaf(a1.z, w, acc[6]);
            acc[7]  = fmaf(a1.w, w, acc[7]);
            acc[8]  = fmaf(a2.x, w, acc[8]);
            acc[9]  = fmaf(a2.y, w, acc[9]);
            acc[10] = fmaf(a2.z, w, acc[10]);
            acc[11] = fmaf(a2.w, w, acc[11]);
            acc[12] = fmaf(a3.x, w, acc[12]);
            acc[13] = fmaf(a3.y, w, acc[13]);
            acc[14] = fmaf(a3.z, w, acc[14]);
            acc[15] = fmaf(a3.w, w, acc[15]);
        }
#pragma unroll
        for (int r = 0; r < 16; r++) ts[r][j] = fast_tanh(acc[r]);
    }
    __syncthreads();

    {
        const int r = tid >> 4, kk = tid & 15;
        float l = gb2[kk];
#pragma unroll 8
        for (int i = 0; i < H_SZ; i += 4) {
            float4 t4 = *(const float4*)&ts[r][i];
            l = fmaf(t4.x, gw2s[(i + 0) * K_SZ + kk], l);
            l = fmaf(t4.y, gw2s[(i + 1) * K_SZ + kk], l);
            l = fmaf(t4.z, gw2s[(i + 2) * K_SZ + kk], l);
            l = fmaf(t4.w, gw2s[(i + 3) * K_SZ + kk], l);
        }
        float m = l;
#pragma unroll
        for (int o = 8; o > 0; o >>= 1)
            m = fmaxf(m, __shfl_xor_sync(0xffffffffu, m, o));
        float e = __expf(l - m);
        float s = e;
#pragma unroll
        for (int o = 8; o > 0; o >>= 1)
            s += __shfl_xor_sync(0xffffffffu, s, o);
        g_gates[(b0 + r) * K_SZ + kk] = e / s;
    }
}

// ---------------------------------------------------------------------------
// Expert GEMM, fp16: acc = sum_d a*b (=16*true). 128x128 CTA, 2 CTAs/SM.
// Epilogue stores PRE-tanh (acc/16 + b2) fp16.
// ---------------------------------------------------------------------------
__device__ __forceinline__ void cp_B(int c, int k, int n0, uint32_t stage) {
    const int tid = threadIdx.x;
    const __half* src = g_Bhi + ((size_t)(k * D_SZ + c * BK)) * D_SZ + n0;
    uint32_t bs = stage + A_BYTES;
#pragma unroll
    for (int i = 0; i < 4; i++) {
        int idx = tid + i * 256;
        int row = idx >> 4, ch = idx & 15;
        cp16(bs + row * (SB * 2) + ch * 16, src + (size_t)row * D_SZ + ch * 8);
    }
}

__device__ __forceinline__ void cp_A(int c, int k, int b0, uint32_t stage) {
    const int tid = threadIdx.x;
    const __half* src = g_A + ((size_t)k * B_SZ + b0) * D_SZ + c * BK;
#pragma unroll
    for (int i = 0; i < 4; i++) {
        int idx = tid + i * 256;
        int m = idx >> 3, ch = idx & 7;
        cp16(stage + m * (SA * 2) + ch * 16, src + (size_t)m * D_SZ + ch * 8);
    }
}

__global__ void __launch_bounds__(256, 2)
expert_gemm_kernel(const float* __restrict__ b2) {
    extern __shared__ __align__(128) char sm[];
    __shared__ float s_b2[BN];

    const int tid = threadIdx.x, wid = tid >> 5, lane = tid & 31;
    const int b0 = blockIdx.x * BM, ny = blockIdx.y, k = blockIdx.z;
    const int n0 = ny * BN;
    const int wm = (wid >> 2) * 64, wn = (wid & 3) * 32;
    const uint32_t smb = smem_u32(sm);

    if (tid < BN) s_b2[tid] = b2[k * D_SZ + n0 + tid];

    const int row16 = (lane & 7) + ((lane >> 3) & 1) * 8;
    const int seg8  = ((lane >> 4) & 1) * 8;

    float acc[4][4][4];
#pragma unroll
    for (int a = 0; a < 4; a++)
#pragma unroll
        for (int b = 0; b < 4; b++)
#pragma unroll
            for (int q = 0; q < 4; q++) acc[a][b][q] = 0.0f;

    // prologue: stages 0,1
#pragma unroll
    for (int s = 0; s < 2; s++) {
        uint32_t st = smb + (uint32_t)s * STAGE;
        cp_A(s, k, b0, st);
        cp_B(s, k, n0, st);
        asm volatile("cp.async.commit_group;");
    }

    for (int c = 0; c < NITER; c++) {
        const uint32_t st = smb + (uint32_t)(c % NSTAGE) * STAGE;
        if (c < NITER - 1)
            asm volatile("cp.async.wait_group 1;" ::: "memory");
        else
            asm volatile("cp.async.wait_group 0;" ::: "memory");
        __syncthreads();

        if (c + 2 < NITER) {
            const uint32_t nst = smb + (uint32_t)((c + 2) % NSTAGE) * STAGE;
            cp_A(c + 2, k, b0, nst);
            cp_B(c + 2, k, n0, nst);
            asm volatile("cp.async.commit_group;");
        }

        const uint32_t As = st, Bh = st + A_BYTES;
#pragma unroll
        for (int kk = 0; kk < 4; kk++) {
            uint32_t ah[4][4];
#pragma unroll
            for (int mb = 0; mb < 4; mb++)
                ldsm4(ah[mb], As + (uint32_t)((wm + mb * 16 + row16) * (SA * 2) +
                                              (kk * 16 + seg8) * 2));
#pragma unroll
            for (int p = 0; p < 2; p++) {
                uint32_t bh[4];
                ldsm4t(bh, Bh + (uint32_t)((kk * 16 + row16) * (SB * 2) +
                                           (wn + p * 16 + seg8) * 2));
#pragma unroll
                for (int mb = 0; mb < 4; mb++) {
                    mma16816(acc[mb][2 * p],     ah[mb], bh[0], bh[1]);
                    mma16816(acc[mb][2 * p + 1], ah[mb], bh[2], bh[3]);
                }
            }
        }
    }

    // Epilogue: store pre-tanh (acc/16 + b2) fp16.
    {
        const int q = lane >> 2, c2 = (lane & 3) * 2;
#pragma unroll
        for (int mb = 0; mb < 4; mb++) {
            const int r0 = wm + mb * 16 + q;
            __half* o0 = &g_raw[((size_t)(b0 + r0) * K_SZ + k) * D_SZ + n0];
            __half* o1 = &g_raw[((size_t)(b0 + r0 + 8) * K_SZ + k) * D_SZ + n0];
#pragma unroll
            for (int nb = 0; nb < 4; nb++) {
                const int e = wn + nb * 8 + c2;
                float bb0 = s_b2[e], bb1 = s_b2[e + 1];
                float v0 = fmaf(acc[mb][nb][0], 0.0625f, bb0);
                float v1 = fmaf(acc[mb][nb][1], 0.0625f, bb1);
                float v2 = fmaf(acc[mb][nb][2], 0.0625f, bb0);
                float v3 = fmaf(acc[mb][nb][3], 0.0625f, bb1);
                *(__half2*)(o0 + e) = __floats2half2_rn(v0, v1);
                *(__half2*)(o1 + e) = __floats2half2_rn(v2, v3);
            }
        }
    }
}

// ---------------------------------------------------------------------------
// Combine: tanh -> smem, per-k LN stats, weighted sum -> theta, x'.
// ---------------------------------------------------------------------------
__global__ void __launch_bounds__(256) combine_kernel(
    const float* __restrict__ x_l, const float* __restrict__ ln_g,
    const float* __restrict__ ln_b, const float* __restrict__ theta0,
    float* __restrict__ out) {
    __shared__ float sv[K_SZ][SVR];
    __shared__ float th[D_SZ];
    __shared__ float s_sum[K_SZ], s_sq[K_SZ], s_a[K_SZ], s_am[K_SZ];
    const int b = blockIdx.x;
    const int tid = threadIdx.x;

    const __half2* rawb = (const __half2*)&g_raw[(size_t)b * K_SZ * D_SZ];
#pragma unroll
    for (int kk = 0; kk < K_SZ; kk++) {
        float2 f = __half22float2(rawb[kk * (D_SZ / 2) + tid]);
        sv[kk][2 * tid]     = fast_tanh(f.x);
        sv[kk][2 * tid + 1] = fast_tanh(f.y);
    }
    __syncthreads();

    {
        const int k = tid >> 4, sub = tid & 15;
        float s = 0.0f, q = 0.0f;
#pragma unroll
        for (int j = 0; j < 32; j++) {
            float v = sv[k][sub + j * 16];
            s += v;
            q = fmaf(v, v, q);
        }
#pragma unroll
        for (int o = 8; o > 0; o >>= 1) {
            s += __shfl_xor_sync(0xffffffffu, s, o);
            q += __shfl_xor_sync(0xffffffffu, q, o);
        }
        if (sub == 0) {
            s_sum[k] = s;
            s_sq[k] = q;
        }
    }
    __syncthreads();

    if (tid < K_SZ) {
        float mu = s_sum[tid] * (1.0f / (float)D_SZ);
        float var = s_sq[tid] * (1.0f / (float)D_SZ) - mu * mu;
        float rs = rsqrtf(var + LN_EPS);
        float a = g_gates[b * K_SZ + tid] * rs;
        s_a[tid] = a;
        s_am[tid] = a * mu;
    }
    __syncthreads();

    float cc = 0.0f;
#pragma unroll
    for (int kk = 0; kk < K_SZ; kk++) cc += s_am[kk];

    {
        float ax = 0.0f, ay = 0.0f;
#pragma unroll
        for (int kk = 0; kk < K_SZ; kk++) {
            float2 f = *(const float2*)&sv[kk][2 * tid];
            ax = fmaf(s_a[kk], f.x, ax);
            ay = fmaf(s_a[kk], f.y, ay);
        }
        float2 lg = *(const float2*)&ln_g[2 * tid];
        float2 lb = *(const float2*)&ln_b[2 * tid];
        float2 t0 = *(const float2*)&theta0[2 * tid];
        float tx = fmaf(lg.x, ax - cc, lb.x) + t0.x;
        float ty = fmaf(lg.y, ay - cc, lb.y) + t0.y;
        th[2 * tid] = tx;
        th[2 * tid + 1] = ty;
        *(float2*)&out[(size_t)B_SZ * XP_DIM + (size_t)b * D_SZ + 2 * tid] =
            make_float2(tx, ty);
    }
    __syncthreads();

    if (tid < XP_DIM) {
        float xp = 0.0f;
#pragma unroll
        for (int i = 0; i < IN_DIM; i++)
            xp = fmaf(x_l[b * IN_DIM + i], th[i * XP_DIM + tid], xp);
        out[b * XP_DIM + tid] = xp;
    }
}

// ---------------------------------------------------------------------------
extern "C" void kernel_launch(void* const* d_in, const int* in_sizes, int n_in,
                              void* d_out, int out_size) {
    const float* h_prev = (const float*)d_in[0];
    const float* x_l    = (const float*)d_in[1];
    const float* x_ext  = (const float*)d_in[2];
    const float* w1     = (const float*)d_in[3];
    const float* b1     = (const float*)d_in[4];
    const float* w2     = (const float*)d_in[5];
    const float* b2     = (const float*)d_in[6];
    const float* gw1    = (const float*)d_in[7];
    const float* gb1    = (const float*)d_in[8];
    const float* gw2    = (const float*)d_in[9];
    const float* gb2    = (const float*)d_in[10];
    const float* ln_g   = (const float*)d_in[11];
    const float* ln_b   = (const float*)d_in[12];
    const float* th0    = (const float*)d_in[13];
    float* out = (float*)d_out;

    cudaFuncSetAttribute(expert_gemm_kernel,
                         cudaFuncAttributeMaxDynamicSharedMemorySize, GEMM_SMEM);

    prep_kernel<<<NB_PREP, 256>>>(w2, x_ext, w1, b1, h_prev, gw1, gb1, gw2, gb2);
    expert_gemm_kernel<<<dim3(B_SZ / BM, D_SZ / BN, K_SZ), 256, GEMM_SMEM>>>(b2);
    combine_kernel<<<B_SZ, 256>>>(x_l, ln_g, ln_b, th0, out);
}